// round 4
// baseline (speedup 1.0000x reference)
#include <cuda_runtime.h>
#include <cuda_bf16.h>
#include <cstdint>

#define CC   128
#define BB   8
#define EE   8
#define NG   4
#define HWPIX 4096
#define IMG  524288   // 128*64*64
#define YSZ  4194304  // 8*128*64*64

__device__ float g_x0[BB * CC];
__device__ float g_w[NG * BB * EE];

// ---------------------------------------------------------------------------
// Kernel 1: batch-mean features
// ---------------------------------------------------------------------------
__global__ void mean_kernel(const float* __restrict__ x) {
    int bc = blockIdx.x;
    const float4* p = (const float4*)(x + (size_t)bc * HWPIX);
    float s = 0.f;
    for (int i = threadIdx.x; i < 1024; i += 256) {
        float4 v = p[i];
        s += (v.x + v.y) + (v.z + v.w);
    }
    for (int o = 16; o; o >>= 1) s += __shfl_xor_sync(0xffffffffu, s, o);
    __shared__ float sm[8];
    if ((threadIdx.x & 31) == 0) sm[threadIdx.x >> 5] = s;
    __syncthreads();
    if (threadIdx.x < 8) {
        float v = sm[threadIdx.x];
        for (int o = 4; o; o >>= 1) v += __shfl_xor_sync(0xffu, v, o);
        if (threadIdx.x == 0) g_x0[bc] = v * (1.0f / 4096.0f);
    }
}

// ---------------------------------------------------------------------------
// Kernel 2: gates
// ---------------------------------------------------------------------------
__global__ void gate_kernel(const float* __restrict__ g1, const float* __restrict__ g2,
                            const float* __restrict__ g3, const float* __restrict__ g4,
                            float* __restrict__ loss_out) {
    int lane = threadIdx.x;
    int g = lane >> 3, b = lane & 7;
    const float* G = (g == 0) ? g1 : (g == 1) ? g2 : (g == 2) ? g3 : g4;
    const float* x0 = &g_x0[b * CC];

    float lg[8];
#pragma unroll
    for (int e = 0; e < 8; e++) lg[e] = 0.f;
    for (int c = 0; c < CC; c++) {
        float xv = x0[c];
#pragma unroll
        for (int e = 0; e < 8; e++) lg[e] += xv * G[c * 8 + e];
    }
    float m = lg[0];
#pragma unroll
    for (int e = 1; e < 8; e++) m = fmaxf(m, lg[e]);
    float p[8], sum = 0.f;
#pragma unroll
    for (int e = 0; e < 8; e++) { p[e] = expf(lg[e] - m); sum += p[e]; }
    float inv = 1.f / sum;
#pragma unroll
    for (int e = 0; e < 8; e++) p[e] *= inv;

    int i1 = 0;
#pragma unroll
    for (int e = 1; e < 8; e++) if (p[e] > p[i1]) i1 = e;
    int i2 = (i1 == 0) ? 1 : 0;
#pragma unroll
    for (int e = 0; e < 8; e++) { if (e == i1 || e == i2) continue; if (p[e] > p[i2]) i2 = e; }
    float m2 = fmaxf(p[i1], p[i2]);
    float e1 = expf(p[i1] - m2), e2 = expf(p[i2] - m2);
    float winv = 1.f / (e1 + e2);

    float* wrow = &g_w[(g * 8 + b) * 8];
#pragma unroll
    for (int e = 0; e < 8; e++) wrow[e] = 0.f;
    wrow[i1] = e1 * winv;
    wrow[i2] = e2 * winv;

    float u[8];
#pragma unroll
    for (int e = 0; e < 8; e++) {
        u[e] = p[e];
        for (int o = 1; o < 8; o <<= 1) u[e] += __shfl_xor_sync(0xffffffffu, u[e], o);
    }
    __shared__ float sl[4];
    if (b == 0) {
        float mu = 0.f;
#pragma unroll
        for (int e = 0; e < 8; e++) mu += u[e];
        mu *= (1.0f / 8.0f);
        float var = 0.f;
#pragma unroll
        for (int e = 0; e < 8; e++) { float d = u[e] - mu; var += d * d; }
        var *= (1.0f / 7.0f);
        sl[g] = var / (mu * mu + 1e-10f);
    }
    __syncwarp();
    if (lane == 0) loss_out[0] = sl[0] + sl[1] + sl[2] + sl[3];
}

// ---------------------------------------------------------------------------
// Main fused kernel (round 4): bf16x3 tensor-core MMA.
// Grid 512 = b(8) x row(64). 256 threads = 8 warps.
// D[px=64, co=128]: warp (wq,wh) owns 16px x 64co.
// GEMM1: K = 1152 (k = tap*128 + ci), 18 chunks of 64k, double-buffered.
// ---------------------------------------------------------------------------

// smem byte offsets
#define SXH   0                 // x hi: 198 rows x 256B (row R = ky*66+col, 128 ci bf16)
#define SXL   50688
#define WB    101376            // 4 bufs x 16384B: whi0, whi1, wlo0, wlo1
#define UTH   166912            // u_t hi: 64 rows x 256B
#define UTL   183296
#define SWG   199680            // 32 floats
#define SPARTB 199808           // 128 floats
#define SSCB  200320            // 64 floats
#define SMEM_BYTES 200576

__device__ __forceinline__ void ldsm4(uint32_t a, uint32_t& r0, uint32_t& r1,
                                      uint32_t& r2, uint32_t& r3) {
    asm volatile("ldmatrix.sync.aligned.m8n8.x4.shared.b16 {%0,%1,%2,%3}, [%4];"
                 : "=r"(r0), "=r"(r1), "=r"(r2), "=r"(r3) : "r"(a));
}
__device__ __forceinline__ void ldsm4t(uint32_t a, uint32_t& r0, uint32_t& r1,
                                       uint32_t& r2, uint32_t& r3) {
    asm volatile("ldmatrix.sync.aligned.m8n8.x4.trans.shared.b16 {%0,%1,%2,%3}, [%4];"
                 : "=r"(r0), "=r"(r1), "=r"(r2), "=r"(r3) : "r"(a));
}
__device__ __forceinline__ void mma16816(float* d, uint32_t a0, uint32_t a1,
                                         uint32_t a2, uint32_t a3,
                                         uint32_t b0, uint32_t b1) {
    asm volatile(
        "mma.sync.aligned.m16n8k16.row.col.f32.bf16.bf16.f32 "
        "{%0,%1,%2,%3},{%4,%5,%6,%7},{%8,%9},{%0,%1,%2,%3};"
        : "+f"(d[0]), "+f"(d[1]), "+f"(d[2]), "+f"(d[3])
        : "r"(a0), "r"(a1), "r"(a2), "r"(a3), "r"(b0), "r"(b1));
}
// pack two floats into (hi-pair, lo-pair) bf16x2 words
__device__ __forceinline__ void split2(float v0, float v1, uint32_t& hi, uint32_t& lo) {
    __nv_bfloat16 h0 = __float2bfloat16(v0), h1 = __float2bfloat16(v1);
    float f0 = __bfloat162float(h0), f1 = __bfloat162float(h1);
    __nv_bfloat16 l0 = __float2bfloat16(v0 - f0), l1 = __float2bfloat16(v1 - f1);
    __nv_bfloat162 ph; ph.x = h0; ph.y = h1;
    __nv_bfloat162 pl; pl.x = l0; pl.y = l1;
    hi = *(uint32_t*)&ph;
    lo = *(uint32_t*)&pl;
}

// ldmatrix address helpers (swizzled rows of 256B: byte = row*256 + (coff ^ ((row&7)<<4)))
__device__ __forceinline__ uint32_t amat_addr(uint32_t base, int R0, int ci0, int lane) {
    int sel = lane >> 3;
    int r = R0 + (lane & 7) + ((sel & 1) << 3);
    int cb = (ci0 + ((sel >> 1) << 3)) * 2;
    return base + r * 256 + (cb ^ ((r & 7) << 4));
}

__global__ void __launch_bounds__(256, 1)
moe_main(const float* __restrict__ x,
         const float* __restrict__ Wc_all, const float* __restrict__ bc_all,
         const float* __restrict__ Wp_all, const float* __restrict__ bp_all,
         float* __restrict__ out) {
    extern __shared__ char smem[];
    const uint32_t sb = (uint32_t)__cvta_generic_to_shared(smem);
    float* swg   = (float*)(smem + SWG);
    float* spart = (float*)(smem + SPARTB);
    float* ssc   = (float*)(smem + SSCB);

    const int tid  = threadIdx.x;
    const int lane = tid & 31;
    const int warp = tid >> 5;
    const int wq = warp >> 1;      // px group (0..3) -> px wq*16..
    const int wh = warp & 1;       // co half -> co wh*64..
    const int b   = blockIdx.x >> 6;
    const int row = blockIdx.x & 63;
    const int gq = lane >> 2, t4 = lane & 3;   // frag row group / col group

    if (tid < 32) {
        int g = tid >> 3, e = tid & 7;
        swg[tid] = g_w[(g * 8 + b) * 8 + e];
    }

    // ---- load x strip (3 image rows, 66 cols incl. halo, 128 ci), split bf16 ----
    {
        const float* xb = x + (size_t)b * IMG;
        for (int it = 0; it < 48; ++it) {
            int rid = warp + it * 8;           // 0..383 = ky*128 + ci
            int ky = rid >> 7, ci = rid & 127;
            int gr = row - 1 + ky;
#pragma unroll
            for (int cl = 0; cl < 3; ++cl) {
                int c = lane + cl * 32;        // col 0..65
                if (cl == 2 && lane >= 2) break;
                int gc = c - 1;
                float v = 0.f;
                if ((unsigned)gr < 64u && (unsigned)gc < 64u)
                    v = xb[ci * HWPIX + gr * 64 + gc];
                __nv_bfloat16 h = __float2bfloat16(v);
                __nv_bfloat16 l = __float2bfloat16(v - __bfloat162float(h));
                int R = ky * 66 + c;
                uint32_t off = R * 256 + ((ci * 2) ^ ((R & 7) << 4));
                *(__nv_bfloat16*)(smem + SXH + off) = h;
                *(__nv_bfloat16*)(smem + SXL + off) = l;
            }
        }
    }

    // y accumulators: [gate][frag(=co octet)][4]
    float yreg[NG][8][4];
#pragma unroll
    for (int g = 0; g < NG; g++)
#pragma unroll
        for (int f = 0; f < 8; f++)
#pragma unroll
            for (int i = 0; i < 4; i++) yreg[g][f][i] = 0.f;

    float acc[8][4];

    for (int e = 0; e < EE; ++e) {
        float wg0 = swg[e], wg1 = swg[8 + e], wg2 = swg[16 + e], wg3 = swg[24 + e];
        __syncthreads();   // swg ready (first iter) / prev expert done with bufs
        if (wg0 == 0.f && wg1 == 0.f && wg2 == 0.f && wg3 == 0.f) continue;

        const float* Wc = Wc_all + (size_t)e * (CC * 1152);
        const float* Wp = Wp_all + (size_t)e * 16384;

        // W_caps chunk loader: chunk cc -> tap j=cc>>1, ci-half h=cc&1, buffer bf
        const int co0w = (tid & 63) * 2;     // this thread's co pair
        const int igw  = tid >> 6;           // k subgroup
        auto loadW = [&](int cc, int bf) {
            int j = cc >> 1, h = cc & 1;
            const float* base0 = Wc + (size_t)co0w * 1152 + j;
            const float* base1 = base0 + 1152;
#pragma unroll
            for (int i = 0; i < 16; ++i) {
                int r = igw * 16 + i;
                int ci = h * 64 + r;
                float v0 = __ldg(base0 + ci * 9);
                float v1 = __ldg(base1 + ci * 9);
                uint32_t hi, lo;
                split2(v0, v1, hi, lo);
                uint32_t off = r * 256 + ((co0w * 2) ^ ((r & 7) << 4));
                *(uint32_t*)(smem + WB + bf * 16384 + off) = hi;
                *(uint32_t*)(smem + WB + 32768 + bf * 16384 + off) = lo;
            }
        };

        loadW(0, 0);
        loadW(1, 1);
#pragma unroll
        for (int f = 0; f < 8; f++)
#pragma unroll
            for (int i = 0; i < 4; i++) acc[f][i] = 0.f;
        __syncthreads();

        // ---- GEMM1 mainloop: 18 chunks ----
        for (int cc = 0; cc < 18; ++cc) {
            const int bf = cc & 1;
            const int j = cc >> 1, h = cc & 1;
            const int ky = j / 3, kx = j - 3 * (j / 3);
            const int R0 = ky * 66 + kx + wq * 16;
            const uint32_t whb = sb + WB + bf * 16384;
            const uint32_t wlb = whb + 32768;
#pragma unroll
            for (int ks = 0; ks < 4; ++ks) {
                const int ci0 = h * 64 + ks * 16;
                uint32_t ah0, ah1, ah2, ah3, al0, al1, al2, al3;
                ldsm4(amat_addr(sb + SXH, R0, ci0, lane), ah0, ah1, ah2, ah3);
                ldsm4(amat_addr(sb + SXL, R0, ci0, lane), al0, al1, al2, al3);
#pragma unroll
                for (int nn = 0; nn < 4; ++nn) {
                    const int co0 = wh * 64 + nn * 16;
                    uint32_t bh0, bh1, bh2, bh3, bl0, bl1, bl2, bl3;
                    // B addr: rows = k (ks*16..), cols = co
                    uint32_t ba = amat_addr(whb, ks * 16, co0, lane);
                    uint32_t bal = amat_addr(wlb, ks * 16, co0, lane);
                    ldsm4t(ba, bh0, bh1, bh2, bh3);
                    ldsm4t(bal, bl0, bl1, bl2, bl3);
                    float* d0 = acc[nn * 2];
                    float* d1 = acc[nn * 2 + 1];
                    mma16816(d0, ah0, ah1, ah2, ah3, bh0, bh1);
                    mma16816(d0, ah0, ah1, ah2, ah3, bl0, bl1);
                    mma16816(d0, al0, al1, al2, al3, bh0, bh1);
                    mma16816(d1, ah0, ah1, ah2, ah3, bh2, bh3);
                    mma16816(d1, ah0, ah1, ah2, ah3, bl2, bl3);
                    mma16816(d1, al0, al1, al2, al3, bh2, bh3);
                }
            }
            __syncthreads();
            if (cc + 2 < 18) loadW(cc + 2, bf);
        }
        // NOTE: after last chunk there was a __syncthreads(); bufs now free.

        // ---- epilogue: bias + sum of squares ----
        float s0 = 0.f, s1 = 0.f;
#pragma unroll
        for (int f = 0; f < 8; ++f) {
            int co = wh * 64 + f * 8 + t4 * 2;
            float bc0 = __ldg(&bc_all[e * CC + co]);
            float bc1 = __ldg(&bc_all[e * CC + co + 1]);
            acc[f][0] += bc0; acc[f][1] += bc1;
            acc[f][2] += bc0; acc[f][3] += bc1;
            s0 = fmaf(acc[f][0], acc[f][0], s0); s0 = fmaf(acc[f][1], acc[f][1], s0);
            s1 = fmaf(acc[f][2], acc[f][2], s1); s1 = fmaf(acc[f][3], acc[f][3], s1);
        }
        s0 += __shfl_xor_sync(0xffffffffu, s0, 1);
        s0 += __shfl_xor_sync(0xffffffffu, s0, 2);
        s1 += __shfl_xor_sync(0xffffffffu, s1, 1);
        s1 += __shfl_xor_sync(0xffffffffu, s1, 2);
        if (t4 == 0) {
            spart[wh * 64 + wq * 16 + gq] = s0;
            spart[wh * 64 + wq * 16 + gq + 8] = s1;
        }
        // load W_proj into the (free) W buffers, transposed+split
        {
#pragma unroll
            for (int i = 0; i < 32; ++i) {
                int ci = igw * 32 + i;
                float v0 = __ldg(Wp + co0w * 128 + ci);
                float v1 = __ldg(Wp + (co0w + 1) * 128 + ci);
                uint32_t hi, lo;
                split2(v0, v1, hi, lo);
                int bf2 = ci >> 6, r = ci & 63;
                uint32_t off = r * 256 + ((co0w * 2) ^ ((r & 7) << 4));
                *(uint32_t*)(smem + WB + bf2 * 16384 + off) = hi;
                *(uint32_t*)(smem + WB + 32768 + bf2 * 16384 + off) = lo;
            }
        }
        __syncthreads();
        if (tid < 64) {
            float sn = spart[tid] + spart[64 + tid];
            ssc[tid] = sn / (1.f + sn) / (sqrtf(sn) + 1e-8f);
        }
        __syncthreads();
        // scale + store u_t (bf16 hi/lo, row = px, 128 ci)
        {
            int px0 = wq * 16 + gq, px1 = px0 + 8;
            float sc0 = ssc[px0], sc1 = ssc[px1];
#pragma unroll
            for (int f = 0; f < 8; ++f) {
                int co = wh * 64 + f * 8 + t4 * 2;
                uint32_t hi, lo;
                split2(acc[f][0] * sc0, acc[f][1] * sc0, hi, lo);
                uint32_t off0 = px0 * 256 + ((co * 2) ^ ((px0 & 7) << 4));
                *(uint32_t*)(smem + UTH + off0) = hi;
                *(uint32_t*)(smem + UTL + off0) = lo;
                split2(acc[f][2] * sc1, acc[f][3] * sc1, hi, lo);
                uint32_t off1 = px1 * 256 + ((co * 2) ^ ((px1 & 7) << 4));
                *(uint32_t*)(smem + UTH + off1) = hi;
                *(uint32_t*)(smem + UTL + off1) = lo;
            }
        }
        __syncthreads();

        // ---- GEMM2: D2[64px,128co2] = u_t @ WpT, K=128 ----
#pragma unroll
        for (int f = 0; f < 8; f++)
#pragma unroll
            for (int i = 0; i < 4; i++) acc[f][i] = 0.f;
#pragma unroll
        for (int ks = 0; ks < 8; ++ks) {
            int kg = ks * 16;
            int bf2 = kg >> 6, kr = kg & 63;
            uint32_t whb = sb + WB + bf2 * 16384;
            uint32_t wlb = whb + 32768;
            uint32_t ah0, ah1, ah2, ah3, al0, al1, al2, al3;
            ldsm4(amat_addr(sb + UTH, wq * 16, kg, lane), ah0, ah1, ah2, ah3);
            ldsm4(amat_addr(sb + UTL, wq * 16, kg, lane), al0, al1, al2, al3);
#pragma unroll
            for (int nn = 0; nn < 4; ++nn) {
                int co0 = wh * 64 + nn * 16;
                uint32_t bh0, bh1, bh2, bh3, bl0, bl1, bl2, bl3;
                ldsm4t(amat_addr(whb, kr, co0, lane), bh0, bh1, bh2, bh3);
                ldsm4t(amat_addr(wlb, kr, co0, lane), bl0, bl1, bl2, bl3);
                float* d0 = acc[nn * 2];
                float* d1 = acc[nn * 2 + 1];
                mma16816(d0, ah0, ah1, ah2, ah3, bh0, bh1);
                mma16816(d0, ah0, ah1, ah2, ah3, bl0, bl1);
                mma16816(d0, al0, al1, al2, al3, bh0, bh1);
                mma16816(d1, ah0, ah1, ah2, ah3, bh2, bh3);
                mma16816(d1, ah0, ah1, ah2, ah3, bl2, bl3);
                mma16816(d1, al0, al1, al2, al3, bh2, bh3);
            }
        }
        // bias + 4-gate weighted accumulation (fragment-resident)
#pragma unroll
        for (int f = 0; f < 8; ++f) {
            int co = wh * 64 + f * 8 + t4 * 2;
            float bp0 = __ldg(&bp_all[e * CC + co]);
            float bp1 = __ldg(&bp_all[e * CC + co + 1]);
            float v0 = acc[f][0] + bp0, v1 = acc[f][1] + bp1;
            float v2 = acc[f][2] + bp0, v3 = acc[f][3] + bp1;
            yreg[0][f][0] = fmaf(wg0, v0, yreg[0][f][0]); yreg[0][f][1] = fmaf(wg0, v1, yreg[0][f][1]);
            yreg[0][f][2] = fmaf(wg0, v2, yreg[0][f][2]); yreg[0][f][3] = fmaf(wg0, v3, yreg[0][f][3]);
            yreg[1][f][0] = fmaf(wg1, v0, yreg[1][f][0]); yreg[1][f][1] = fmaf(wg1, v1, yreg[1][f][1]);
            yreg[1][f][2] = fmaf(wg1, v2, yreg[1][f][2]); yreg[1][f][3] = fmaf(wg1, v3, yreg[1][f][3]);
            yreg[2][f][0] = fmaf(wg2, v0, yreg[2][f][0]); yreg[2][f][1] = fmaf(wg2, v1, yreg[2][f][1]);
            yreg[2][f][2] = fmaf(wg2, v2, yreg[2][f][2]); yreg[2][f][3] = fmaf(wg2, v3, yreg[2][f][3]);
            yreg[3][f][0] = fmaf(wg3, v0, yreg[3][f][0]); yreg[3][f][1] = fmaf(wg3, v1, yreg[3][f][1]);
            yreg[3][f][2] = fmaf(wg3, v2, yreg[3][f][2]); yreg[3][f][3] = fmaf(wg3, v3, yreg[3][f][3]);
        }
    }

    // ---- final store: stage each gate through smem for coalesced STG.128 ----
    float* stage = (float*)(smem + WB);           // [128 co][68 px] fp32
    int px0 = wq * 16 + gq, px1 = px0 + 8;
#pragma unroll 1
    for (int g = 0; g < NG; ++g) {
        __syncthreads();
#pragma unroll
        for (int f = 0; f < 8; ++f) {
            int co = wh * 64 + f * 8 + t4 * 2;
            stage[co * 68 + px0]       = yreg[g][f][0];
            stage[(co + 1) * 68 + px0] = yreg[g][f][1];
            stage[co * 68 + px1]       = yreg[g][f][2];
            stage[(co + 1) * 68 + px1] = yreg[g][f][3];
        }
        __syncthreads();
        float* og = out + (size_t)g * YSZ + (size_t)b * IMG + (size_t)row * 64;
        int p4 = (tid & 15) * 4;
#pragma unroll
        for (int it = 0; it < 8; ++it) {
            int co = (tid >> 4) + it * 16;
            float4 v = *(float4*)&stage[co * 68 + p4];
            *(float4*)&og[(size_t)co * HWPIX + p4] = v;
        }
    }
}

// ---------------------------------------------------------------------------
extern "C" void kernel_launch(void* const* d_in, const int* in_sizes, int n_in,
                              void* d_out, int out_size) {
    const float* x  = (const float*)d_in[0];
    const float* g1 = (const float*)d_in[1];
    const float* g2 = (const float*)d_in[2];
    const float* g3 = (const float*)d_in[3];
    const float* g4 = (const float*)d_in[4];
    const float* Wc = (const float*)d_in[5];
    const float* bc = (const float*)d_in[6];
    const float* Wp = (const float*)d_in[7];
    const float* bp = (const float*)d_in[8];
    float* out = (float*)d_out;

    cudaFuncSetAttribute(moe_main, cudaFuncAttributeMaxDynamicSharedMemorySize, SMEM_BYTES);

    mean_kernel<<<BB * CC, 256>>>(x);
    gate_kernel<<<1, 32>>>(g1, g2, g3, g4, out + (out_size - 1));
    moe_main<<<512, 256, SMEM_BYTES>>>(x, Wc, bc, Wp, bp, out);
}

// round 5
// speedup vs baseline: 5.3669x; 5.3669x over previous
#include <cuda_runtime.h>
#include <cuda_bf16.h>
#include <cstdint>

#define CC   128
#define BB   8
#define EE   8
#define NG   4
#define HWPIX 4096
#define IMG  524288   // 128*64*64
#define YSZ  4194304  // 8*128*64*64

__device__ float g_x0[BB * CC];
__device__ float g_w[NG * BB * EE];

// Pre-split weights (swizzled 16KB chunk images, ready for cp.async -> smem)
__device__ uint32_t g_wc_hi[EE * 18 * 4096];   // [e][chunk][r*64 + word]
__device__ uint32_t g_wc_lo[EE * 18 * 4096];
__device__ uint32_t g_wp_hi[EE * 2 * 4096];
__device__ uint32_t g_wp_lo[EE * 2 * 4096];

// ---------------------------------------------------------------------------
// Kernel 1: batch-mean features
// ---------------------------------------------------------------------------
__global__ void mean_kernel(const float* __restrict__ x) {
    int bc = blockIdx.x;
    const float4* p = (const float4*)(x + (size_t)bc * HWPIX);
    float s = 0.f;
    for (int i = threadIdx.x; i < 1024; i += 256) {
        float4 v = p[i];
        s += (v.x + v.y) + (v.z + v.w);
    }
    for (int o = 16; o; o >>= 1) s += __shfl_xor_sync(0xffffffffu, s, o);
    __shared__ float sm[8];
    if ((threadIdx.x & 31) == 0) sm[threadIdx.x >> 5] = s;
    __syncthreads();
    if (threadIdx.x < 8) {
        float v = sm[threadIdx.x];
        for (int o = 4; o; o >>= 1) v += __shfl_xor_sync(0xffu, v, o);
        if (threadIdx.x == 0) g_x0[bc] = v * (1.0f / 4096.0f);
    }
}

// ---------------------------------------------------------------------------
// Kernel 2: gates
// ---------------------------------------------------------------------------
__global__ void gate_kernel(const float* __restrict__ g1, const float* __restrict__ g2,
                            const float* __restrict__ g3, const float* __restrict__ g4,
                            float* __restrict__ loss_out) {
    int lane = threadIdx.x;
    int g = lane >> 3, b = lane & 7;
    const float* G = (g == 0) ? g1 : (g == 1) ? g2 : (g == 2) ? g3 : g4;
    const float* x0 = &g_x0[b * CC];

    float lg[8];
#pragma unroll
    for (int e = 0; e < 8; e++) lg[e] = 0.f;
    for (int c = 0; c < CC; c++) {
        float xv = x0[c];
#pragma unroll
        for (int e = 0; e < 8; e++) lg[e] += xv * G[c * 8 + e];
    }
    float m = lg[0];
#pragma unroll
    for (int e = 1; e < 8; e++) m = fmaxf(m, lg[e]);
    float p[8], sum = 0.f;
#pragma unroll
    for (int e = 0; e < 8; e++) { p[e] = expf(lg[e] - m); sum += p[e]; }
    float inv = 1.f / sum;
#pragma unroll
    for (int e = 0; e < 8; e++) p[e] *= inv;

    int i1 = 0;
#pragma unroll
    for (int e = 1; e < 8; e++) if (p[e] > p[i1]) i1 = e;
    int i2 = (i1 == 0) ? 1 : 0;
#pragma unroll
    for (int e = 0; e < 8; e++) { if (e == i1 || e == i2) continue; if (p[e] > p[i2]) i2 = e; }
    float m2 = fmaxf(p[i1], p[i2]);
    float e1 = expf(p[i1] - m2), e2 = expf(p[i2] - m2);
    float winv = 1.f / (e1 + e2);

    float* wrow = &g_w[(g * 8 + b) * 8];
#pragma unroll
    for (int e = 0; e < 8; e++) wrow[e] = 0.f;
    wrow[i1] = e1 * winv;
    wrow[i2] = e2 * winv;

    float u[8];
#pragma unroll
    for (int e = 0; e < 8; e++) {
        u[e] = p[e];
        for (int o = 1; o < 8; o <<= 1) u[e] += __shfl_xor_sync(0xffffffffu, u[e], o);
    }
    __shared__ float sl[4];
    if (b == 0) {
        float mu = 0.f;
#pragma unroll
        for (int e = 0; e < 8; e++) mu += u[e];
        mu *= (1.0f / 8.0f);
        float var = 0.f;
#pragma unroll
        for (int e = 0; e < 8; e++) { float d = u[e] - mu; var += d * d; }
        var *= (1.0f / 7.0f);
        sl[g] = var / (mu * mu + 1e-10f);
    }
    __syncwarp();
    if (lane == 0) loss_out[0] = sl[0] + sl[1] + sl[2] + sl[3];
}

// ---------------------------------------------------------------------------
// split helper
// ---------------------------------------------------------------------------
__device__ __forceinline__ void split2(float v0, float v1, uint32_t& hi, uint32_t& lo) {
    __nv_bfloat16 h0 = __float2bfloat16(v0), h1 = __float2bfloat16(v1);
    float f0 = __bfloat162float(h0), f1 = __bfloat162float(h1);
    __nv_bfloat16 l0 = __float2bfloat16(v0 - f0), l1 = __float2bfloat16(v1 - f1);
    __nv_bfloat162 ph; ph.x = h0; ph.y = h1;
    __nv_bfloat162 pl; pl.x = l0; pl.y = l1;
    hi = *(uint32_t*)&ph;
    lo = *(uint32_t*)&pl;
}

// ---------------------------------------------------------------------------
// Prep kernel A: W_caps -> split-bf16 swizzled chunk images.
// chunk cc = j*2 + h (tap j 0..8, ci-half h). Row r = ci within half (0..63),
// 128 co bf16 per row, swizzled byte offset r*256 + ((co*2)^((r&7)<<4)).
// Grid: 8*18 blocks, 256 threads.
// ---------------------------------------------------------------------------
__global__ void prep_wc(const float* __restrict__ Wc_all) {
    int e = blockIdx.x / 18, cc = blockIdx.x % 18;
    int j = cc >> 1, h = cc & 1;
    const float* Wc = Wc_all + (size_t)e * (CC * 1152);
    uint32_t* oh = g_wc_hi + (size_t)blockIdx.x * 4096;
    uint32_t* ol = g_wc_lo + (size_t)blockIdx.x * 4096;
#pragma unroll 4
    for (int idx = threadIdx.x; idx < 4096; idx += 256) {
        int r = idx >> 6, cop = idx & 63;
        int co = cop * 2, ci = h * 64 + r;
        float v0 = __ldg(Wc + (size_t)co * 1152 + ci * 9 + j);
        float v1 = __ldg(Wc + (size_t)(co + 1) * 1152 + ci * 9 + j);
        uint32_t hi, lo;
        split2(v0, v1, hi, lo);
        uint32_t woff = (r * 256 + ((co * 2) ^ ((r & 7) << 4))) >> 2;
        oh[woff] = hi;
        ol[woff] = lo;
    }
}

// ---------------------------------------------------------------------------
// Prep kernel B: W_proj -> split-bf16 swizzled chunk images (2 chunks/expert).
// chunk bf2 covers ci in [bf2*64, bf2*64+64). Grid: 8*2 blocks, 256 threads.
// ---------------------------------------------------------------------------
__global__ void prep_wp(const float* __restrict__ Wp_all) {
    int e = blockIdx.x >> 1, bf2 = blockIdx.x & 1;
    const float* Wp = Wp_all + (size_t)e * 16384;
    uint32_t* oh = g_wp_hi + (size_t)blockIdx.x * 4096;
    uint32_t* ol = g_wp_lo + (size_t)blockIdx.x * 4096;
#pragma unroll 4
    for (int idx = threadIdx.x; idx < 4096; idx += 256) {
        int r = idx >> 6, cop = idx & 63;
        int co = cop * 2, ci = bf2 * 64 + r;
        float v0 = __ldg(Wp + (size_t)co * 128 + ci);
        float v1 = __ldg(Wp + (size_t)(co + 1) * 128 + ci);
        uint32_t hi, lo;
        split2(v0, v1, hi, lo);
        uint32_t woff = (r * 256 + ((co * 2) ^ ((r & 7) << 4))) >> 2;
        oh[woff] = hi;
        ol[woff] = lo;
    }
}

// ---------------------------------------------------------------------------
// Main fused kernel: bf16x3 tensor-core MMA; weights streamed via cp.async.
// ---------------------------------------------------------------------------

#define SXH   0
#define SXL   50688
#define WB    101376            // 4 bufs x 16384B: whi0, whi1, wlo0, wlo1
#define UTH   166912
#define UTL   183296
#define SWG   199680
#define SPARTB 199808
#define SSCB  200320
#define SMEM_BYTES 200576

__device__ __forceinline__ void ldsm4(uint32_t a, uint32_t& r0, uint32_t& r1,
                                      uint32_t& r2, uint32_t& r3) {
    asm volatile("ldmatrix.sync.aligned.m8n8.x4.shared.b16 {%0,%1,%2,%3}, [%4];"
                 : "=r"(r0), "=r"(r1), "=r"(r2), "=r"(r3) : "r"(a));
}
__device__ __forceinline__ void ldsm4t(uint32_t a, uint32_t& r0, uint32_t& r1,
                                       uint32_t& r2, uint32_t& r3) {
    asm volatile("ldmatrix.sync.aligned.m8n8.x4.trans.shared.b16 {%0,%1,%2,%3}, [%4];"
                 : "=r"(r0), "=r"(r1), "=r"(r2), "=r"(r3) : "r"(a));
}
__device__ __forceinline__ void mma16816(float* d, uint32_t a0, uint32_t a1,
                                         uint32_t a2, uint32_t a3,
                                         uint32_t b0, uint32_t b1) {
    asm volatile(
        "mma.sync.aligned.m16n8k16.row.col.f32.bf16.bf16.f32 "
        "{%0,%1,%2,%3},{%4,%5,%6,%7},{%8,%9},{%0,%1,%2,%3};"
        : "+f"(d[0]), "+f"(d[1]), "+f"(d[2]), "+f"(d[3])
        : "r"(a0), "r"(a1), "r"(a2), "r"(a3), "r"(b0), "r"(b1));
}
__device__ __forceinline__ uint32_t amat_addr(uint32_t base, int R0, int ci0, int lane) {
    int sel = lane >> 3;
    int r = R0 + (lane & 7) + ((sel & 1) << 3);
    int cb = (ci0 + ((sel >> 1) << 3)) * 2;
    return base + r * 256 + (cb ^ ((r & 7) << 4));
}
__device__ __forceinline__ void cp16s(uint32_t dst, const void* src) {
    asm volatile("cp.async.ca.shared.global [%0], [%1], 16;" :: "r"(dst), "l"(src));
}
#define CP_COMMIT() asm volatile("cp.async.commit_group;")
#define CP_WAIT1()  asm volatile("cp.async.wait_group 1;")
#define CP_WAIT0()  asm volatile("cp.async.wait_group 0;")

__global__ void __launch_bounds__(256, 1)
moe_main(const float* __restrict__ x,
         const float* __restrict__ bc_all, const float* __restrict__ bp_all,
         float* __restrict__ out) {
    extern __shared__ char smem[];
    const uint32_t sb = (uint32_t)__cvta_generic_to_shared(smem);
    float* swg   = (float*)(smem + SWG);
    float* spart = (float*)(smem + SPARTB);
    float* ssc   = (float*)(smem + SSCB);

    const int tid  = threadIdx.x;
    const int lane = tid & 31;
    const int warp = tid >> 5;
    const int wq = warp >> 1;
    const int wh = warp & 1;
    const int b   = blockIdx.x >> 6;
    const int row = blockIdx.x & 63;
    const int gq = lane >> 2, t4 = lane & 3;

    if (tid < 32) {
        int g = tid >> 3, e = tid & 7;
        swg[tid] = g_w[(g * 8 + b) * 8 + e];
    }

    // ---- x strip (3 rows, 66 cols, 128 ci), split bf16, swizzled ----
    {
        const float* xb = x + (size_t)b * IMG;
        for (int it = 0; it < 48; ++it) {
            int rid = warp + it * 8;
            int ky = rid >> 7, ci = rid & 127;
            int gr = row - 1 + ky;
#pragma unroll
            for (int cl = 0; cl < 3; ++cl) {
                int c = lane + cl * 32;
                if (cl == 2 && lane >= 2) break;
                int gc = c - 1;
                float v = 0.f;
                if ((unsigned)gr < 64u && (unsigned)gc < 64u)
                    v = xb[ci * HWPIX + gr * 64 + gc];
                __nv_bfloat16 h = __float2bfloat16(v);
                __nv_bfloat16 l = __float2bfloat16(v - __bfloat162float(h));
                int R = ky * 66 + c;
                uint32_t off = R * 256 + ((ci * 2) ^ ((R & 7) << 4));
                *(__nv_bfloat16*)(smem + SXH + off) = h;
                *(__nv_bfloat16*)(smem + SXL + off) = l;
            }
        }
    }

    float yreg[NG][8][4];
#pragma unroll
    for (int g = 0; g < NG; g++)
#pragma unroll
        for (int f = 0; f < 8; f++)
#pragma unroll
            for (int i = 0; i < 4; i++) yreg[g][f][i] = 0.f;

    float acc[8][4];

    for (int e = 0; e < EE; ++e) {
        float wg0 = swg[e], wg1 = swg[8 + e], wg2 = swg[16 + e], wg3 = swg[24 + e];
        __syncthreads();   // swg ready / prev expert done with WB
        if (wg0 == 0.f && wg1 == 0.f && wg2 == 0.f && wg3 == 0.f) continue;

        // cp.async one 32KB chunk (hi+lo) into buffer bf
        auto loadW = [&](int cc, int bf) {
            const uint32_t* srcH = g_wc_hi + (size_t)(e * 18 + cc) * 4096;
            const uint32_t* srcL = g_wc_lo + (size_t)(e * 18 + cc) * 4096;
#pragma unroll
            for (int k = 0; k < 4; ++k) {
                int i = tid + k * 256;
                cp16s(sb + WB + bf * 16384 + i * 16, srcH + i * 4);
                cp16s(sb + WB + 32768 + bf * 16384 + i * 16, srcL + i * 4);
            }
            CP_COMMIT();
        };

        loadW(0, 0);
        loadW(1, 1);
#pragma unroll
        for (int f = 0; f < 8; f++)
#pragma unroll
            for (int i = 0; i < 4; i++) acc[f][i] = 0.f;

        // ---- GEMM1: 18 chunks of 64k ----
        for (int cc = 0; cc < 18; ++cc) {
            if (cc == 17) { CP_WAIT0(); } else { CP_WAIT1(); }
            __syncthreads();
            const int bf = cc & 1;
            const int j = cc >> 1;
            const int ky = j / 3, kx = j - 3 * (j / 3);
            const int R0 = ky * 66 + kx + wq * 16;
            const int h = cc & 1;
            const uint32_t whb = sb + WB + bf * 16384;
            const uint32_t wlb = whb + 32768;
#pragma unroll
            for (int ks = 0; ks < 4; ++ks) {
                const int ci0 = h * 64 + ks * 16;
                uint32_t ah0, ah1, ah2, ah3, al0, al1, al2, al3;
                ldsm4(amat_addr(sb + SXH, R0, ci0, lane), ah0, ah1, ah2, ah3);
                ldsm4(amat_addr(sb + SXL, R0, ci0, lane), al0, al1, al2, al3);
#pragma unroll
                for (int nn = 0; nn < 4; ++nn) {
                    const int co0 = wh * 64 + nn * 16;
                    uint32_t bh0, bh1, bh2, bh3, bl0, bl1, bl2, bl3;
                    ldsm4t(amat_addr(whb, ks * 16, co0, lane), bh0, bh1, bh2, bh3);
                    ldsm4t(amat_addr(wlb, ks * 16, co0, lane), bl0, bl1, bl2, bl3);
                    float* d0 = acc[nn * 2];
                    float* d1 = acc[nn * 2 + 1];
                    mma16816(d0, ah0, ah1, ah2, ah3, bh0, bh1);
                    mma16816(d0, ah0, ah1, ah2, ah3, bl0, bl1);
                    mma16816(d0, al0, al1, al2, al3, bh0, bh1);
                    mma16816(d1, ah0, ah1, ah2, ah3, bh2, bh3);
                    mma16816(d1, ah0, ah1, ah2, ah3, bl2, bl3);
                    mma16816(d1, al0, al1, al2, al3, bh2, bh3);
                }
            }
            __syncthreads();
            if (cc + 2 < 18) loadW(cc + 2, bf);
        }

        // issue W_proj copies (hidden under squash epilogue)
        {
            const uint32_t* sH = g_wp_hi + (size_t)e * 8192;
            const uint32_t* sL = g_wp_lo + (size_t)e * 8192;
#pragma unroll
            for (int k = 0; k < 8; ++k) {
                int i = tid + k * 256;                  // 0..2047 (two 16KB bufs)
                cp16s(sb + WB + i * 16, sH + i * 4);
                cp16s(sb + WB + 32768 + i * 16, sL + i * 4);
            }
            CP_COMMIT();
        }

        // ---- epilogue: bias + sum of squares ----
        float s0 = 0.f, s1 = 0.f;
#pragma unroll
        for (int f = 0; f < 8; ++f) {
            int co = wh * 64 + f * 8 + t4 * 2;
            float bc0 = __ldg(&bc_all[e * CC + co]);
            float bc1 = __ldg(&bc_all[e * CC + co + 1]);
            acc[f][0] += bc0; acc[f][1] += bc1;
            acc[f][2] += bc0; acc[f][3] += bc1;
            s0 = fmaf(acc[f][0], acc[f][0], s0); s0 = fmaf(acc[f][1], acc[f][1], s0);
            s1 = fmaf(acc[f][2], acc[f][2], s1); s1 = fmaf(acc[f][3], acc[f][3], s1);
        }
        s0 += __shfl_xor_sync(0xffffffffu, s0, 1);
        s0 += __shfl_xor_sync(0xffffffffu, s0, 2);
        s1 += __shfl_xor_sync(0xffffffffu, s1, 1);
        s1 += __shfl_xor_sync(0xffffffffu, s1, 2);
        if (t4 == 0) {
            spart[wh * 64 + wq * 16 + gq] = s0;
            spart[wh * 64 + wq * 16 + gq + 8] = s1;
        }
        __syncthreads();
        if (tid < 64) {
            float sn = spart[tid] + spart[64 + tid];
            ssc[tid] = sn / (1.f + sn) / (sqrtf(sn) + 1e-8f);
        }
        __syncthreads();
        // scale + store u_t (split bf16; row = px)
        {
            int px0 = wq * 16 + gq, px1 = px0 + 8;
            float sc0 = ssc[px0], sc1 = ssc[px1];
#pragma unroll
            for (int f = 0; f < 8; ++f) {
                int co = wh * 64 + f * 8 + t4 * 2;
                uint32_t hi, lo;
                split2(acc[f][0] * sc0, acc[f][1] * sc0, hi, lo);
                uint32_t off0 = px0 * 256 + ((co * 2) ^ ((px0 & 7) << 4));
                *(uint32_t*)(smem + UTH + off0) = hi;
                *(uint32_t*)(smem + UTL + off0) = lo;
                split2(acc[f][2] * sc1, acc[f][3] * sc1, hi, lo);
                uint32_t off1 = px1 * 256 + ((co * 2) ^ ((px1 & 7) << 4));
                *(uint32_t*)(smem + UTH + off1) = hi;
                *(uint32_t*)(smem + UTL + off1) = lo;
            }
        }
        CP_WAIT0();
        __syncthreads();

        // ---- GEMM2: K=128 ----
#pragma unroll
        for (int f = 0; f < 8; f++)
#pragma unroll
            for (int i = 0; i < 4; i++) acc[f][i] = 0.f;
#pragma unroll
        for (int ks = 0; ks < 8; ++ks) {
            int kg = ks * 16;
            int bf2 = kg >> 6, kr = kg & 63;
            uint32_t whb = sb + WB + bf2 * 16384;
            uint32_t wlb = whb + 32768;
            uint32_t ah0, ah1, ah2, ah3, al0, al1, al2, al3;
            ldsm4(amat_addr(sb + UTH, wq * 16, kg, lane), ah0, ah1, ah2, ah3);
            ldsm4(amat_addr(sb + UTL, wq * 16, kg, lane), al0, al1, al2, al3);
#pragma unroll
            for (int nn = 0; nn < 4; ++nn) {
                int co0 = wh * 64 + nn * 16;
                uint32_t bh0, bh1, bh2, bh3, bl0, bl1, bl2, bl3;
                ldsm4t(amat_addr(whb, kr, co0, lane), bh0, bh1, bh2, bh3);
                ldsm4t(amat_addr(wlb, kr, co0, lane), bl0, bl1, bl2, bl3);
                float* d0 = acc[nn * 2];
                float* d1 = acc[nn * 2 + 1];
                mma16816(d0, ah0, ah1, ah2, ah3, bh0, bh1);
                mma16816(d0, ah0, ah1, ah2, ah3, bl0, bl1);
                mma16816(d0, al0, al1, al2, al3, bh0, bh1);
                mma16816(d1, ah0, ah1, ah2, ah3, bh2, bh3);
                mma16816(d1, ah0, ah1, ah2, ah3, bl2, bl3);
                mma16816(d1, al0, al1, al2, al3, bh2, bh3);
            }
        }
        // bias + 4-gate weighted accumulation
#pragma unroll
        for (int f = 0; f < 8; ++f) {
            int co = wh * 64 + f * 8 + t4 * 2;
            float bp0 = __ldg(&bp_all[e * CC + co]);
            float bp1 = __ldg(&bp_all[e * CC + co + 1]);
            float v0 = acc[f][0] + bp0, v1 = acc[f][1] + bp1;
            float v2 = acc[f][2] + bp0, v3 = acc[f][3] + bp1;
            yreg[0][f][0] = fmaf(wg0, v0, yreg[0][f][0]); yreg[0][f][1] = fmaf(wg0, v1, yreg[0][f][1]);
            yreg[0][f][2] = fmaf(wg0, v2, yreg[0][f][2]); yreg[0][f][3] = fmaf(wg0, v3, yreg[0][f][3]);
            yreg[1][f][0] = fmaf(wg1, v0, yreg[1][f][0]); yreg[1][f][1] = fmaf(wg1, v1, yreg[1][f][1]);
            yreg[1][f][2] = fmaf(wg1, v2, yreg[1][f][2]); yreg[1][f][3] = fmaf(wg1, v3, yreg[1][f][3]);
            yreg[2][f][0] = fmaf(wg2, v0, yreg[2][f][0]); yreg[2][f][1] = fmaf(wg2, v1, yreg[2][f][1]);
            yreg[2][f][2] = fmaf(wg2, v2, yreg[2][f][2]); yreg[2][f][3] = fmaf(wg2, v3, yreg[2][f][3]);
            yreg[3][f][0] = fmaf(wg3, v0, yreg[3][f][0]); yreg[3][f][1] = fmaf(wg3, v1, yreg[3][f][1]);
            yreg[3][f][2] = fmaf(wg3, v2, yreg[3][f][2]); yreg[3][f][3] = fmaf(wg3, v3, yreg[3][f][3]);
        }
    }

    // ---- final store: stage each gate through smem for coalesced STG.128 ----
    float* stage = (float*)(smem + WB);
    int px0 = wq * 16 + gq, px1 = px0 + 8;
#pragma unroll 1
    for (int g = 0; g < NG; ++g) {
        __syncthreads();
#pragma unroll
        for (int f = 0; f < 8; ++f) {
            int co = wh * 64 + f * 8 + t4 * 2;
            stage[co * 68 + px0]       = yreg[g][f][0];
            stage[(co + 1) * 68 + px0] = yreg[g][f][1];
            stage[co * 68 + px1]       = yreg[g][f][2];
            stage[(co + 1) * 68 + px1] = yreg[g][f][3];
        }
        __syncthreads();
        float* og = out + (size_t)g * YSZ + (size_t)b * IMG + (size_t)row * 64;
        int p4 = (tid & 15) * 4;
#pragma unroll
        for (int it = 0; it < 8; ++it) {
            int co = (tid >> 4) + it * 16;
            float4 v = *(float4*)&stage[co * 68 + p4];
            *(float4*)&og[(size_t)co * HWPIX + p4] = v;
        }
    }
}

// ---------------------------------------------------------------------------
extern "C" void kernel_launch(void* const* d_in, const int* in_sizes, int n_in,
                              void* d_out, int out_size) {
    const float* x  = (const float*)d_in[0];
    const float* g1 = (const float*)d_in[1];
    const float* g2 = (const float*)d_in[2];
    const float* g3 = (const float*)d_in[3];
    const float* g4 = (const float*)d_in[4];
    const float* Wc = (const float*)d_in[5];
    const float* bc = (const float*)d_in[6];
    const float* Wp = (const float*)d_in[7];
    const float* bp = (const float*)d_in[8];
    float* out = (float*)d_out;

    cudaFuncSetAttribute(moe_main, cudaFuncAttributeMaxDynamicSharedMemorySize, SMEM_BYTES);

    mean_kernel<<<BB * CC, 256>>>(x);
    gate_kernel<<<1, 32>>>(g1, g2, g3, g4, out + (out_size - 1));
    prep_wc<<<EE * 18, 256>>>(Wc);
    prep_wp<<<EE * 2, 256>>>(Wp);
    moe_main<<<512, 256, SMEM_BYTES>>>(x, bc, bp, out);
}

// round 6
// speedup vs baseline: 5.3819x; 1.0028x over previous
#include <cuda_runtime.h>
#include <cuda_bf16.h>
#include <cstdint>

#define CC   128
#define BB   8
#define EE   8
#define NG   4
#define HWPIX 4096
#define IMG  524288   // 128*64*64
#define YSZ  4194304  // 8*128*64*64

__device__ float g_x0[BB * CC];
__device__ float g_w[NG * BB * EE];

// Pre-split weights (swizzled 16KB chunk images, ready for cp.async -> smem)
__device__ uint32_t g_wc_hi[EE * 18 * 4096];   // [e][chunk][r*64 + word]
__device__ uint32_t g_wc_lo[EE * 18 * 4096];
__device__ uint32_t g_wp_hi[EE * 2 * 4096];
__device__ uint32_t g_wp_lo[EE * 2 * 4096];

// ---------------------------------------------------------------------------
// Kernel 1: batch-mean features
// ---------------------------------------------------------------------------
__global__ void mean_kernel(const float* __restrict__ x) {
    int bc = blockIdx.x;
    const float4* p = (const float4*)(x + (size_t)bc * HWPIX);
    float s = 0.f;
    for (int i = threadIdx.x; i < 1024; i += 256) {
        float4 v = p[i];
        s += (v.x + v.y) + (v.z + v.w);
    }
    for (int o = 16; o; o >>= 1) s += __shfl_xor_sync(0xffffffffu, s, o);
    __shared__ float sm[8];
    if ((threadIdx.x & 31) == 0) sm[threadIdx.x >> 5] = s;
    __syncthreads();
    if (threadIdx.x < 8) {
        float v = sm[threadIdx.x];
        for (int o = 4; o; o >>= 1) v += __shfl_xor_sync(0xffu, v, o);
        if (threadIdx.x == 0) g_x0[bc] = v * (1.0f / 4096.0f);
    }
}

// ---------------------------------------------------------------------------
// Kernel 2: gates
// ---------------------------------------------------------------------------
__global__ void gate_kernel(const float* __restrict__ g1, const float* __restrict__ g2,
                            const float* __restrict__ g3, const float* __restrict__ g4,
                            float* __restrict__ loss_out) {
    int lane = threadIdx.x;
    int g = lane >> 3, b = lane & 7;
    const float* G = (g == 0) ? g1 : (g == 1) ? g2 : (g == 2) ? g3 : g4;
    const float* x0 = &g_x0[b * CC];

    float lg[8];
#pragma unroll
    for (int e = 0; e < 8; e++) lg[e] = 0.f;
    for (int c = 0; c < CC; c++) {
        float xv = x0[c];
#pragma unroll
        for (int e = 0; e < 8; e++) lg[e] += xv * G[c * 8 + e];
    }
    float m = lg[0];
#pragma unroll
    for (int e = 1; e < 8; e++) m = fmaxf(m, lg[e]);
    float p[8], sum = 0.f;
#pragma unroll
    for (int e = 0; e < 8; e++) { p[e] = expf(lg[e] - m); sum += p[e]; }
    float inv = 1.f / sum;
#pragma unroll
    for (int e = 0; e < 8; e++) p[e] *= inv;

    int i1 = 0;
#pragma unroll
    for (int e = 1; e < 8; e++) if (p[e] > p[i1]) i1 = e;
    int i2 = (i1 == 0) ? 1 : 0;
#pragma unroll
    for (int e = 0; e < 8; e++) { if (e == i1 || e == i2) continue; if (p[e] > p[i2]) i2 = e; }
    float m2 = fmaxf(p[i1], p[i2]);
    float e1 = expf(p[i1] - m2), e2 = expf(p[i2] - m2);
    float winv = 1.f / (e1 + e2);

    float* wrow = &g_w[(g * 8 + b) * 8];
#pragma unroll
    for (int e = 0; e < 8; e++) wrow[e] = 0.f;
    wrow[i1] = e1 * winv;
    wrow[i2] = e2 * winv;

    float u[8];
#pragma unroll
    for (int e = 0; e < 8; e++) {
        u[e] = p[e];
        for (int o = 1; o < 8; o <<= 1) u[e] += __shfl_xor_sync(0xffffffffu, u[e], o);
    }
    __shared__ float sl[4];
    if (b == 0) {
        float mu = 0.f;
#pragma unroll
        for (int e = 0; e < 8; e++) mu += u[e];
        mu *= (1.0f / 8.0f);
        float var = 0.f;
#pragma unroll
        for (int e = 0; e < 8; e++) { float d = u[e] - mu; var += d * d; }
        var *= (1.0f / 7.0f);
        sl[g] = var / (mu * mu + 1e-10f);
    }
    __syncwarp();
    if (lane == 0) loss_out[0] = sl[0] + sl[1] + sl[2] + sl[3];
}

// ---------------------------------------------------------------------------
// split helper
// ---------------------------------------------------------------------------
__device__ __forceinline__ void split2(float v0, float v1, uint32_t& hi, uint32_t& lo) {
    __nv_bfloat16 h0 = __float2bfloat16(v0), h1 = __float2bfloat16(v1);
    float f0 = __bfloat162float(h0), f1 = __bfloat162float(h1);
    __nv_bfloat16 l0 = __float2bfloat16(v0 - f0), l1 = __float2bfloat16(v1 - f1);
    __nv_bfloat162 ph; ph.x = h0; ph.y = h1;
    __nv_bfloat162 pl; pl.x = l0; pl.y = l1;
    hi = *(uint32_t*)&ph;
    lo = *(uint32_t*)&pl;
}

// ---------------------------------------------------------------------------
// Prep kernel A: W_caps -> split-bf16 swizzled chunk images.
// chunk cc = j*2 + h (tap j 0..8, ci-half h). Row r = ci within half (0..63),
// 128 co bf16 per row, swizzled byte offset r*256 + ((co*2)^((r&7)<<4)).
// Grid: 8*18 blocks, 256 threads.
// ---------------------------------------------------------------------------
__global__ void prep_wc(const float* __restrict__ Wc_all) {
    int e = blockIdx.x / 18, cc = blockIdx.x % 18;
    int j = cc >> 1, h = cc & 1;
    const float* Wc = Wc_all + (size_t)e * (CC * 1152);
    uint32_t* oh = g_wc_hi + (size_t)blockIdx.x * 4096;
    uint32_t* ol = g_wc_lo + (size_t)blockIdx.x * 4096;
#pragma unroll 4
    for (int idx = threadIdx.x; idx < 4096; idx += 256) {
        int r = idx >> 6, cop = idx & 63;
        int co = cop * 2, ci = h * 64 + r;
        float v0 = __ldg(Wc + (size_t)co * 1152 + ci * 9 + j);
        float v1 = __ldg(Wc + (size_t)(co + 1) * 1152 + ci * 9 + j);
        uint32_t hi, lo;
        split2(v0, v1, hi, lo);
        uint32_t woff = (r * 256 + ((co * 2) ^ ((r & 7) << 4))) >> 2;
        oh[woff] = hi;
        ol[woff] = lo;
    }
}

// ---------------------------------------------------------------------------
// Prep kernel B: W_proj -> split-bf16 swizzled chunk images (2 chunks/expert).
// chunk bf2 covers ci in [bf2*64, bf2*64+64). Grid: 8*2 blocks, 256 threads.
// ---------------------------------------------------------------------------
__global__ void prep_wp(const float* __restrict__ Wp_all) {
    int e = blockIdx.x >> 1, bf2 = blockIdx.x & 1;
    const float* Wp = Wp_all + (size_t)e * 16384;
    uint32_t* oh = g_wp_hi + (size_t)blockIdx.x * 4096;
    uint32_t* ol = g_wp_lo + (size_t)blockIdx.x * 4096;
#pragma unroll 4
    for (int idx = threadIdx.x; idx < 4096; idx += 256) {
        int r = idx >> 6, cop = idx & 63;
        int co = cop * 2, ci = bf2 * 64 + r;
        float v0 = __ldg(Wp + (size_t)co * 128 + ci);
        float v1 = __ldg(Wp + (size_t)(co + 1) * 128 + ci);
        uint32_t hi, lo;
        split2(v0, v1, hi, lo);
        uint32_t woff = (r * 256 + ((co * 2) ^ ((r & 7) << 4))) >> 2;
        oh[woff] = hi;
        ol[woff] = lo;
    }
}

// ---------------------------------------------------------------------------
// Main fused kernel: bf16x3 tensor-core MMA; weights streamed via cp.async.
// ---------------------------------------------------------------------------

#define SXH   0
#define SXL   50688
#define WB    101376            // 4 bufs x 16384B: whi0, whi1, wlo0, wlo1
#define UTH   166912
#define UTL   183296
#define SWG   199680
#define SPARTB 199808
#define SSCB  200320
#define SMEM_BYTES 200576

__device__ __forceinline__ void ldsm4(uint32_t a, uint32_t& r0, uint32_t& r1,
                                      uint32_t& r2, uint32_t& r3) {
    asm volatile("ldmatrix.sync.aligned.m8n8.x4.shared.b16 {%0,%1,%2,%3}, [%4];"
                 : "=r"(r0), "=r"(r1), "=r"(r2), "=r"(r3) : "r"(a));
}
__device__ __forceinline__ void ldsm4t(uint32_t a, uint32_t& r0, uint32_t& r1,
                                       uint32_t& r2, uint32_t& r3) {
    asm volatile("ldmatrix.sync.aligned.m8n8.x4.trans.shared.b16 {%0,%1,%2,%3}, [%4];"
                 : "=r"(r0), "=r"(r1), "=r"(r2), "=r"(r3) : "r"(a));
}
__device__ __forceinline__ void mma16816(float* d, uint32_t a0, uint32_t a1,
                                         uint32_t a2, uint32_t a3,
                                         uint32_t b0, uint32_t b1) {
    asm volatile(
        "mma.sync.aligned.m16n8k16.row.col.f32.bf16.bf16.f32 "
        "{%0,%1,%2,%3},{%4,%5,%6,%7},{%8,%9},{%0,%1,%2,%3};"
        : "+f"(d[0]), "+f"(d[1]), "+f"(d[2]), "+f"(d[3])
        : "r"(a0), "r"(a1), "r"(a2), "r"(a3), "r"(b0), "r"(b1));
}
__device__ __forceinline__ uint32_t amat_addr(uint32_t base, int R0, int ci0, int lane) {
    int sel = lane >> 3;
    int r = R0 + (lane & 7) + ((sel & 1) << 3);
    int cb = (ci0 + ((sel >> 1) << 3)) * 2;
    return base + r * 256 + (cb ^ ((r & 7) << 4));
}
__device__ __forceinline__ void cp16s(uint32_t dst, const void* src) {
    asm volatile("cp.async.ca.shared.global [%0], [%1], 16;" :: "r"(dst), "l"(src));
}
#define CP_COMMIT() asm volatile("cp.async.commit_group;")
#define CP_WAIT1()  asm volatile("cp.async.wait_group 1;")
#define CP_WAIT0()  asm volatile("cp.async.wait_group 0;")

__global__ void __launch_bounds__(256, 1)
moe_main(const float* __restrict__ x,
         const float* __restrict__ bc_all, const float* __restrict__ bp_all,
         float* __restrict__ out) {
    extern __shared__ char smem[];
    const uint32_t sb = (uint32_t)__cvta_generic_to_shared(smem);
    float* swg   = (float*)(smem + SWG);
    float* spart = (float*)(smem + SPARTB);
    float* ssc   = (float*)(smem + SSCB);

    const int tid  = threadIdx.x;
    const int lane = tid & 31;
    const int warp = tid >> 5;
    const int wq = warp >> 1;
    const int wh = warp & 1;
    const int b   = blockIdx.x >> 6;
    const int row = blockIdx.x & 63;
    const int gq = lane >> 2, t4 = lane & 3;

    if (tid < 32) {
        int g = tid >> 3, e = tid & 7;
        swg[tid] = g_w[(g * 8 + b) * 8 + e];
    }

    // ---- x strip (3 rows, 66 cols, 128 ci), split bf16, swizzled ----
    {
        const float* xb = x + (size_t)b * IMG;
        for (int it = 0; it < 48; ++it) {
            int rid = warp + it * 8;
            int ky = rid >> 7, ci = rid & 127;
            int gr = row - 1 + ky;
#pragma unroll
            for (int cl = 0; cl < 3; ++cl) {
                int c = lane + cl * 32;
                if (cl == 2 && lane >= 2) break;
                int gc = c - 1;
                float v = 0.f;
                if ((unsigned)gr < 64u && (unsigned)gc < 64u)
                    v = xb[ci * HWPIX + gr * 64 + gc];
                __nv_bfloat16 h = __float2bfloat16(v);
                __nv_bfloat16 l = __float2bfloat16(v - __bfloat162float(h));
                int R = ky * 66 + c;
                uint32_t off = R * 256 + ((ci * 2) ^ ((R & 7) << 4));
                *(__nv_bfloat16*)(smem + SXH + off) = h;
                *(__nv_bfloat16*)(smem + SXL + off) = l;
            }
        }
    }

    float yreg[NG][8][4];
#pragma unroll
    for (int g = 0; g < NG; g++)
#pragma unroll
        for (int f = 0; f < 8; f++)
#pragma unroll
            for (int i = 0; i < 4; i++) yreg[g][f][i] = 0.f;

    float acc[8][4];

    for (int e = 0; e < EE; ++e) {
        float wg0 = swg[e], wg1 = swg[8 + e], wg2 = swg[16 + e], wg3 = swg[24 + e];
        __syncthreads();   // swg ready / prev expert done with WB
        if (wg0 == 0.f && wg1 == 0.f && wg2 == 0.f && wg3 == 0.f) continue;

        // cp.async one 32KB chunk (hi+lo) into buffer bf
        auto loadW = [&](int cc, int bf) {
            const uint32_t* srcH = g_wc_hi + (size_t)(e * 18 + cc) * 4096;
            const uint32_t* srcL = g_wc_lo + (size_t)(e * 18 + cc) * 4096;
#pragma unroll
            for (int k = 0; k < 4; ++k) {
                int i = tid + k * 256;
                cp16s(sb + WB + bf * 16384 + i * 16, srcH + i * 4);
                cp16s(sb + WB + 32768 + bf * 16384 + i * 16, srcL + i * 4);
            }
            CP_COMMIT();
        };

        loadW(0, 0);
        loadW(1, 1);
#pragma unroll
        for (int f = 0; f < 8; f++)
#pragma unroll
            for (int i = 0; i < 4; i++) acc[f][i] = 0.f;

        // ---- GEMM1: 18 chunks of 64k ----
        for (int cc = 0; cc < 18; ++cc) {
            if (cc == 17) { CP_WAIT0(); } else { CP_WAIT1(); }
            __syncthreads();
            const int bf = cc & 1;
            const int j = cc >> 1;
            const int ky = j / 3, kx = j - 3 * (j / 3);
            const int R0 = ky * 66 + kx + wq * 16;
            const int h = cc & 1;
            const uint32_t whb = sb + WB + bf * 16384;
            const uint32_t wlb = whb + 32768;
#pragma unroll
            for (int ks = 0; ks < 4; ++ks) {
                const int ci0 = h * 64 + ks * 16;
                uint32_t ah0, ah1, ah2, ah3, al0, al1, al2, al3;
                ldsm4(amat_addr(sb + SXH, R0, ci0, lane), ah0, ah1, ah2, ah3);
                ldsm4(amat_addr(sb + SXL, R0, ci0, lane), al0, al1, al2, al3);
#pragma unroll
                for (int nn = 0; nn < 4; ++nn) {
                    const int co0 = wh * 64 + nn * 16;
                    uint32_t bh0, bh1, bh2, bh3, bl0, bl1, bl2, bl3;
                    ldsm4t(amat_addr(whb, ks * 16, co0, lane), bh0, bh1, bh2, bh3);
                    ldsm4t(amat_addr(wlb, ks * 16, co0, lane), bl0, bl1, bl2, bl3);
                    float* d0 = acc[nn * 2];
                    float* d1 = acc[nn * 2 + 1];
                    mma16816(d0, ah0, ah1, ah2, ah3, bh0, bh1);
                    mma16816(d0, ah0, ah1, ah2, ah3, bl0, bl1);
                    mma16816(d0, al0, al1, al2, al3, bh0, bh1);
                    mma16816(d1, ah0, ah1, ah2, ah3, bh2, bh3);
                    mma16816(d1, ah0, ah1, ah2, ah3, bl2, bl3);
                    mma16816(d1, al0, al1, al2, al3, bh2, bh3);
                }
            }
            __syncthreads();
            if (cc + 2 < 18) loadW(cc + 2, bf);
        }

        // issue W_proj copies (hidden under squash epilogue)
        {
            const uint32_t* sH = g_wp_hi + (size_t)e * 8192;
            const uint32_t* sL = g_wp_lo + (size_t)e * 8192;
#pragma unroll
            for (int k = 0; k < 8; ++k) {
                int i = tid + k * 256;                  // 0..2047 (two 16KB bufs)
                cp16s(sb + WB + i * 16, sH + i * 4);
                cp16s(sb + WB + 32768 + i * 16, sL + i * 4);
            }
            CP_COMMIT();
        }

        // ---- epilogue: bias + sum of squares ----
        float s0 = 0.f, s1 = 0.f;
#pragma unroll
        for (int f = 0; f < 8; ++f) {
            int co = wh * 64 + f * 8 + t4 * 2;
            float bc0 = __ldg(&bc_all[e * CC + co]);
            float bc1 = __ldg(&bc_all[e * CC + co + 1]);
            acc[f][0] += bc0; acc[f][1] += bc1;
            acc[f][2] += bc0; acc[f][3] += bc1;
            s0 = fmaf(acc[f][0], acc[f][0], s0); s0 = fmaf(acc[f][1], acc[f][1], s0);
            s1 = fmaf(acc[f][2], acc[f][2], s1); s1 = fmaf(acc[f][3], acc[f][3], s1);
        }
        s0 += __shfl_xor_sync(0xffffffffu, s0, 1);
        s0 += __shfl_xor_sync(0xffffffffu, s0, 2);
        s1 += __shfl_xor_sync(0xffffffffu, s1, 1);
        s1 += __shfl_xor_sync(0xffffffffu, s1, 2);
        if (t4 == 0) {
            spart[wh * 64 + wq * 16 + gq] = s0;
            spart[wh * 64 + wq * 16 + gq + 8] = s1;
        }
        __syncthreads();
        if (tid < 64) {
            float sn = spart[tid] + spart[64 + tid];
            ssc[tid] = sn / (1.f + sn) / (sqrtf(sn) + 1e-8f);
        }
        __syncthreads();
        // scale + store u_t (split bf16; row = px)
        {
            int px0 = wq * 16 + gq, px1 = px0 + 8;
            float sc0 = ssc[px0], sc1 = ssc[px1];
#pragma unroll
            for (int f = 0; f < 8; ++f) {
                int co = wh * 64 + f * 8 + t4 * 2;
                uint32_t hi, lo;
                split2(acc[f][0] * sc0, acc[f][1] * sc0, hi, lo);
                uint32_t off0 = px0 * 256 + ((co * 2) ^ ((px0 & 7) << 4));
                *(uint32_t*)(smem + UTH + off0) = hi;
                *(uint32_t*)(smem + UTL + off0) = lo;
                split2(acc[f][2] * sc1, acc[f][3] * sc1, hi, lo);
                uint32_t off1 = px1 * 256 + ((co * 2) ^ ((px1 & 7) << 4));
                *(uint32_t*)(smem + UTH + off1) = hi;
                *(uint32_t*)(smem + UTL + off1) = lo;
            }
        }
        CP_WAIT0();
        __syncthreads();

        // ---- GEMM2: K=128 ----
#pragma unroll
        for (int f = 0; f < 8; f++)
#pragma unroll
            for (int i = 0; i < 4; i++) acc[f][i] = 0.f;
#pragma unroll
        for (int ks = 0; ks < 8; ++ks) {
            int kg = ks * 16;
            int bf2 = kg >> 6, kr = kg & 63;
            uint32_t whb = sb + WB + bf2 * 16384;
            uint32_t wlb = whb + 32768;
            uint32_t ah0, ah1, ah2, ah3, al0, al1, al2, al3;
            ldsm4(amat_addr(sb + UTH, wq * 16, kg, lane), ah0, ah1, ah2, ah3);
            ldsm4(amat_addr(sb + UTL, wq * 16, kg, lane), al0, al1, al2, al3);
#pragma unroll
            for (int nn = 0; nn < 4; ++nn) {
                int co0 = wh * 64 + nn * 16;
                uint32_t bh0, bh1, bh2, bh3, bl0, bl1, bl2, bl3;
                ldsm4t(amat_addr(whb, kr, co0, lane), bh0, bh1, bh2, bh3);
                ldsm4t(amat_addr(wlb, kr, co0, lane), bl0, bl1, bl2, bl3);
                float* d0 = acc[nn * 2];
                float* d1 = acc[nn * 2 + 1];
                mma16816(d0, ah0, ah1, ah2, ah3, bh0, bh1);
                mma16816(d0, ah0, ah1, ah2, ah3, bl0, bl1);
                mma16816(d0, al0, al1, al2, al3, bh0, bh1);
                mma16816(d1, ah0, ah1, ah2, ah3, bh2, bh3);
                mma16816(d1, ah0, ah1, ah2, ah3, bl2, bl3);
                mma16816(d1, al0, al1, al2, al3, bh2, bh3);
            }
        }
        // bias + 4-gate weighted accumulation
#pragma unroll
        for (int f = 0; f < 8; ++f) {
            int co = wh * 64 + f * 8 + t4 * 2;
            float bp0 = __ldg(&bp_all[e * CC + co]);
            float bp1 = __ldg(&bp_all[e * CC + co + 1]);
            float v0 = acc[f][0] + bp0, v1 = acc[f][1] + bp1;
            float v2 = acc[f][2] + bp0, v3 = acc[f][3] + bp1;
            yreg[0][f][0] = fmaf(wg0, v0, yreg[0][f][0]); yreg[0][f][1] = fmaf(wg0, v1, yreg[0][f][1]);
            yreg[0][f][2] = fmaf(wg0, v2, yreg[0][f][2]); yreg[0][f][3] = fmaf(wg0, v3, yreg[0][f][3]);
            yreg[1][f][0] = fmaf(wg1, v0, yreg[1][f][0]); yreg[1][f][1] = fmaf(wg1, v1, yreg[1][f][1]);
            yreg[1][f][2] = fmaf(wg1, v2, yreg[1][f][2]); yreg[1][f][3] = fmaf(wg1, v3, yreg[1][f][3]);
            yreg[2][f][0] = fmaf(wg2, v0, yreg[2][f][0]); yreg[2][f][1] = fmaf(wg2, v1, yreg[2][f][1]);
            yreg[2][f][2] = fmaf(wg2, v2, yreg[2][f][2]); yreg[2][f][3] = fmaf(wg2, v3, yreg[2][f][3]);
            yreg[3][f][0] = fmaf(wg3, v0, yreg[3][f][0]); yreg[3][f][1] = fmaf(wg3, v1, yreg[3][f][1]);
            yreg[3][f][2] = fmaf(wg3, v2, yreg[3][f][2]); yreg[3][f][3] = fmaf(wg3, v3, yreg[3][f][3]);
        }
    }

    // ---- final store: stage each gate through smem for coalesced STG.128 ----
    float* stage = (float*)(smem + WB);
    int px0 = wq * 16 + gq, px1 = px0 + 8;
#pragma unroll 1
    for (int g = 0; g < NG; ++g) {
        __syncthreads();
#pragma unroll
        for (int f = 0; f < 8; ++f) {
            int co = wh * 64 + f * 8 + t4 * 2;
            stage[co * 68 + px0]       = yreg[g][f][0];
            stage[(co + 1) * 68 + px0] = yreg[g][f][1];
            stage[co * 68 + px1]       = yreg[g][f][2];
            stage[(co + 1) * 68 + px1] = yreg[g][f][3];
        }
        __syncthreads();
        float* og = out + (size_t)g * YSZ + (size_t)b * IMG + (size_t)row * 64;
        int p4 = (tid & 15) * 4;
#pragma unroll
        for (int it = 0; it < 8; ++it) {
            int co = (tid >> 4) + it * 16;
            float4 v = *(float4*)&stage[co * 68 + p4];
            *(float4*)&og[(size_t)co * HWPIX + p4] = v;
        }
    }
}

// ---------------------------------------------------------------------------
extern "C" void kernel_launch(void* const* d_in, const int* in_sizes, int n_in,
                              void* d_out, int out_size) {
    const float* x  = (const float*)d_in[0];
    const float* g1 = (const float*)d_in[1];
    const float* g2 = (const float*)d_in[2];
    const float* g3 = (const float*)d_in[3];
    const float* g4 = (const float*)d_in[4];
    const float* Wc = (const float*)d_in[5];
    const float* bc = (const float*)d_in[6];
    const float* Wp = (const float*)d_in[7];
    const float* bp = (const float*)d_in[8];
    float* out = (float*)d_out;

    cudaFuncSetAttribute(moe_main, cudaFuncAttributeMaxDynamicSharedMemorySize, SMEM_BYTES);

    mean_kernel<<<BB * CC, 256>>>(x);
    gate_kernel<<<1, 32>>>(g1, g2, g3, g4, out + (out_size - 1));
    prep_wc<<<EE * 18, 256>>>(Wc);
    prep_wp<<<EE * 2, 256>>>(Wp);
    moe_main<<<512, 256, SMEM_BYTES>>>(x, bc, bp, out);
}

// round 9
// speedup vs baseline: 5.7799x; 1.0740x over previous
#include <cuda_runtime.h>
#include <cuda_bf16.h>
#include <cuda_fp16.h>
#include <cstdint>

#define CC   128
#define BB   8
#define EE   8
#define NG   4
#define HWPIX 4096
#define IMG  524288   // 128*64*64
#define YSZ  4194304  // 8*128*64*64

__device__ float g_x0[BB * CC];
__device__ float g_w[NG * BB * EE];

// Pre-converted weights (swizzled 16KB chunk images, ready for cp.async -> smem)
// f16 = fp16 rounding of W ; bf = bf16 residual (W - f16(W))
__device__ uint32_t g_wc_f16[EE * 18 * 4096];
__device__ uint32_t g_wc_bf [EE * 18 * 4096];
__device__ uint32_t g_wp_f16[EE * 2 * 4096];
__device__ uint32_t g_wp_bf [EE * 2 * 4096];

// ---------------------------------------------------------------------------
// Kernel 1: batch-mean features
// ---------------------------------------------------------------------------
__global__ void mean_kernel(const float* __restrict__ x) {
    int bc = blockIdx.x;
    const float4* p = (const float4*)(x + (size_t)bc * HWPIX);
    float s = 0.f;
    for (int i = threadIdx.x; i < 1024; i += 256) {
        float4 v = p[i];
        s += (v.x + v.y) + (v.z + v.w);
    }
    for (int o = 16; o; o >>= 1) s += __shfl_xor_sync(0xffffffffu, s, o);
    __shared__ float sm[8];
    if ((threadIdx.x & 31) == 0) sm[threadIdx.x >> 5] = s;
    __syncthreads();
    if (threadIdx.x < 8) {
        float v = sm[threadIdx.x];
        for (int o = 4; o; o >>= 1) v += __shfl_xor_sync(0xffu, v, o);
        if (threadIdx.x == 0) g_x0[bc] = v * (1.0f / 4096.0f);
    }
}

// ---------------------------------------------------------------------------
// Kernel 2: gates
// ---------------------------------------------------------------------------
__global__ void gate_kernel(const float* __restrict__ g1, const float* __restrict__ g2,
                            const float* __restrict__ g3, const float* __restrict__ g4,
                            float* __restrict__ loss_out) {
    int lane = threadIdx.x;
    int g = lane >> 3, b = lane & 7;
    const float* G = (g == 0) ? g1 : (g == 1) ? g2 : (g == 2) ? g3 : g4;
    const float* x0 = &g_x0[b * CC];

    float lg[8];
#pragma unroll
    for (int e = 0; e < 8; e++) lg[e] = 0.f;
    for (int c = 0; c < CC; c++) {
        float xv = x0[c];
#pragma unroll
        for (int e = 0; e < 8; e++) lg[e] += xv * G[c * 8 + e];
    }
    float m = lg[0];
#pragma unroll
    for (int e = 1; e < 8; e++) m = fmaxf(m, lg[e]);
    float p[8], sum = 0.f;
#pragma unroll
    for (int e = 0; e < 8; e++) { p[e] = expf(lg[e] - m); sum += p[e]; }
    float inv = 1.f / sum;
#pragma unroll
    for (int e = 0; e < 8; e++) p[e] *= inv;

    int i1 = 0;
#pragma unroll
    for (int e = 1; e < 8; e++) if (p[e] > p[i1]) i1 = e;
    int i2 = (i1 == 0) ? 1 : 0;
#pragma unroll
    for (int e = 0; e < 8; e++) { if (e == i1 || e == i2) continue; if (p[e] > p[i2]) i2 = e; }
    float m2 = fmaxf(p[i1], p[i2]);
    float e1 = expf(p[i1] - m2), e2 = expf(p[i2] - m2);
    float winv = 1.f / (e1 + e2);

    float* wrow = &g_w[(g * 8 + b) * 8];
#pragma unroll
    for (int e = 0; e < 8; e++) wrow[e] = 0.f;
    wrow[i1] = e1 * winv;
    wrow[i2] = e2 * winv;

    float u[8];
#pragma unroll
    for (int e = 0; e < 8; e++) {
        u[e] = p[e];
        for (int o = 1; o < 8; o <<= 1) u[e] += __shfl_xor_sync(0xffffffffu, u[e], o);
    }
    __shared__ float sl[4];
    if (b == 0) {
        float mu = 0.f;
#pragma unroll
        for (int e = 0; e < 8; e++) mu += u[e];
        mu *= (1.0f / 8.0f);
        float var = 0.f;
#pragma unroll
        for (int e = 0; e < 8; e++) { float d = u[e] - mu; var += d * d; }
        var *= (1.0f / 7.0f);
        sl[g] = var / (mu * mu + 1e-10f);
    }
    __syncwarp();
    if (lane == 0) loss_out[0] = sl[0] + sl[1] + sl[2] + sl[3];
}

// ---------------------------------------------------------------------------
// split helper: pack (fp16 hi pair, bf16 residual pair)
// ---------------------------------------------------------------------------
__device__ __forceinline__ void splitFB(float v0, float v1, uint32_t& hi, uint32_t& lo) {
    __half h0 = __float2half_rn(v0), h1 = __float2half_rn(v1);
    float f0 = __half2float(h0), f1 = __half2float(h1);
    __nv_bfloat16 l0 = __float2bfloat16(v0 - f0), l1 = __float2bfloat16(v1 - f1);
    __half2 ph; ph.x = h0; ph.y = h1;
    __nv_bfloat162 pl; pl.x = l0; pl.y = l1;
    hi = *(uint32_t*)&ph;
    lo = *(uint32_t*)&pl;
}

// ---------------------------------------------------------------------------
// Prep kernel A: W_caps -> fp16 + bf16-residual swizzled chunk images.
// chunk cc = j*2 + h (tap j 0..8, ci-half h). Row r = ci within half (0..63),
// 128 co (2B each) per row, swizzled byte offset r*256 + ((co*2)^((r&7)<<4)).
// ---------------------------------------------------------------------------
__global__ void prep_wc(const float* __restrict__ Wc_all) {
    int e = blockIdx.x / 18, cc = blockIdx.x % 18;
    int j = cc >> 1, h = cc & 1;
    const float* Wc = Wc_all + (size_t)e * (CC * 1152);
    uint32_t* oh = g_wc_f16 + (size_t)blockIdx.x * 4096;
    uint32_t* ol = g_wc_bf  + (size_t)blockIdx.x * 4096;
#pragma unroll 4
    for (int idx = threadIdx.x; idx < 4096; idx += 256) {
        int r = idx >> 6, cop = idx & 63;
        int co = cop * 2, ci = h * 64 + r;
        float v0 = __ldg(Wc + (size_t)co * 1152 + ci * 9 + j);
        float v1 = __ldg(Wc + (size_t)(co + 1) * 1152 + ci * 9 + j);
        uint32_t hi, lo;
        splitFB(v0, v1, hi, lo);
        uint32_t woff = (r * 256 + ((co * 2) ^ ((r & 7) << 4))) >> 2;
        oh[woff] = hi;
        ol[woff] = lo;
    }
}

// ---------------------------------------------------------------------------
// Prep kernel B: W_proj -> fp16 + bf16-residual images (2 chunks/expert).
// ---------------------------------------------------------------------------
__global__ void prep_wp(const float* __restrict__ Wp_all) {
    int e = blockIdx.x >> 1, bf2 = blockIdx.x & 1;
    const float* Wp = Wp_all + (size_t)e * 16384;
    uint32_t* oh = g_wp_f16 + (size_t)blockIdx.x * 4096;
    uint32_t* ol = g_wp_bf  + (size_t)blockIdx.x * 4096;
#pragma unroll 4
    for (int idx = threadIdx.x; idx < 4096; idx += 256) {
        int r = idx >> 6, cop = idx & 63;
        int co = cop * 2, ci = bf2 * 64 + r;
        float v0 = __ldg(Wp + (size_t)co * 128 + ci);
        float v1 = __ldg(Wp + (size_t)(co + 1) * 128 + ci);
        uint32_t hi, lo;
        splitFB(v0, v1, hi, lo);
        uint32_t woff = (r * 256 + ((co * 2) ^ ((r & 7) << 4))) >> 2;
        oh[woff] = hi;
        ol[woff] = lo;
    }
}

// ---------------------------------------------------------------------------
// Main fused kernel: 2-term fp16/bf16 mixed-split tensor-core MMA.
//   D = Ah(f16) * W(f16)  +  Al(bf16 residual) * W(bf16)
// ---------------------------------------------------------------------------

#define SXH   0            // x fp16 hi: 198 rows x 256B
#define SXL   50688        // x bf16 residual
#define WB    101376       // 4 bufs x 16384B: wf16_0, wf16_1, wbf_0, wbf_1
#define UTH   166912       // u fp16 hi
#define UTL   183296       // u bf16 residual
#define SWG   199680
#define SPARTB 199808
#define SSCB  200320
#define SMEM_BYTES 200576

__device__ __forceinline__ void ldsm4(uint32_t a, uint32_t& r0, uint32_t& r1,
                                      uint32_t& r2, uint32_t& r3) {
    asm volatile("ldmatrix.sync.aligned.m8n8.x4.shared.b16 {%0,%1,%2,%3}, [%4];"
                 : "=r"(r0), "=r"(r1), "=r"(r2), "=r"(r3) : "r"(a));
}
__device__ __forceinline__ void ldsm4t(uint32_t a, uint32_t& r0, uint32_t& r1,
                                       uint32_t& r2, uint32_t& r3) {
    asm volatile("ldmatrix.sync.aligned.m8n8.x4.trans.shared.b16 {%0,%1,%2,%3}, [%4];"
                 : "=r"(r0), "=r"(r1), "=r"(r2), "=r"(r3) : "r"(a));
}
__device__ __forceinline__ void mma_bf(float* d, uint32_t a0, uint32_t a1,
                                       uint32_t a2, uint32_t a3,
                                       uint32_t b0, uint32_t b1) {
    asm volatile(
        "mma.sync.aligned.m16n8k16.row.col.f32.bf16.bf16.f32 "
        "{%0,%1,%2,%3},{%4,%5,%6,%7},{%8,%9},{%0,%1,%2,%3};"
        : "+f"(d[0]), "+f"(d[1]), "+f"(d[2]), "+f"(d[3])
        : "r"(a0), "r"(a1), "r"(a2), "r"(a3), "r"(b0), "r"(b1));
}
__device__ __forceinline__ void mma_fp(float* d, uint32_t a0, uint32_t a1,
                                       uint32_t a2, uint32_t a3,
                                       uint32_t b0, uint32_t b1) {
    asm volatile(
        "mma.sync.aligned.m16n8k16.row.col.f32.f16.f16.f32 "
        "{%0,%1,%2,%3},{%4,%5,%6,%7},{%8,%9},{%0,%1,%2,%3};"
        : "+f"(d[0]), "+f"(d[1]), "+f"(d[2]), "+f"(d[3])
        : "r"(a0), "r"(a1), "r"(a2), "r"(a3), "r"(b0), "r"(b1));
}
__device__ __forceinline__ uint32_t amat_addr(uint32_t base, int R0, int ci0, int lane) {
    int sel = lane >> 3;
    int r = R0 + (lane & 7) + ((sel & 1) << 3);
    int cb = (ci0 + ((sel >> 1) << 3)) * 2;
    return base + r * 256 + (cb ^ ((r & 7) << 4));
}
__device__ __forceinline__ void cp16s(uint32_t dst, const void* src) {
    asm volatile("cp.async.ca.shared.global [%0], [%1], 16;" :: "r"(dst), "l"(src));
}
#define CP_COMMIT() asm volatile("cp.async.commit_group;")
#define CP_WAIT1()  asm volatile("cp.async.wait_group 1;")
#define CP_WAIT0()  asm volatile("cp.async.wait_group 0;")

__global__ void __launch_bounds__(256, 1)
moe_main(const float* __restrict__ x,
         const float* __restrict__ bc_all, const float* __restrict__ bp_all,
         float* __restrict__ out) {
    extern __shared__ char smem[];
    const uint32_t sb = (uint32_t)__cvta_generic_to_shared(smem);
    float* swg   = (float*)(smem + SWG);
    float* spart = (float*)(smem + SPARTB);
    float* ssc   = (float*)(smem + SSCB);

    const int tid  = threadIdx.x;
    const int lane = tid & 31;
    const int warp = tid >> 5;
    const int wq = warp >> 1;
    const int wh = warp & 1;
    const int b   = blockIdx.x >> 6;
    const int row = blockIdx.x & 63;
    const int gq = lane >> 2, t4 = lane & 3;

    if (tid < 32) {
        int g = tid >> 3, e = tid & 7;
        swg[tid] = g_w[(g * 8 + b) * 8 + e];
    }

    // ---- x strip (3 rows, 66 cols, 128 ci): fp16 hi + bf16 residual, swizzled ----
    {
        const float* xb = x + (size_t)b * IMG;
        for (int it = 0; it < 48; ++it) {
            int rid = warp + it * 8;
            int ky = rid >> 7, ci = rid & 127;
            int gr = row - 1 + ky;
#pragma unroll
            for (int cl = 0; cl < 3; ++cl) {
                int c = lane + cl * 32;
                if (cl == 2 && lane >= 2) break;
                int gc = c - 1;
                float v = 0.f;
                if ((unsigned)gr < 64u && (unsigned)gc < 64u)
                    v = xb[ci * HWPIX + gr * 64 + gc];
                __half h = __float2half_rn(v);
                __nv_bfloat16 l = __float2bfloat16(v - __half2float(h));
                int R = ky * 66 + c;
                uint32_t off = R * 256 + ((ci * 2) ^ ((R & 7) << 4));
                *(__half*)(smem + SXH + off) = h;
                *(__nv_bfloat16*)(smem + SXL + off) = l;
            }
        }
    }

    float yreg[NG][8][4];
#pragma unroll
    for (int g = 0; g < NG; g++)
#pragma unroll
        for (int f = 0; f < 8; f++)
#pragma unroll
            for (int i = 0; i < 4; i++) yreg[g][f][i] = 0.f;

    float acc[8][4];

    for (int e = 0; e < EE; ++e) {
        float wg0 = swg[e], wg1 = swg[8 + e], wg2 = swg[16 + e], wg3 = swg[24 + e];
        __syncthreads();   // swg ready / prev expert done with WB
        if (wg0 == 0.f && wg1 == 0.f && wg2 == 0.f && wg3 == 0.f) continue;

        auto loadW = [&](int cc, int bf) {
            const uint32_t* srcH = g_wc_f16 + (size_t)(e * 18 + cc) * 4096;
            const uint32_t* srcL = g_wc_bf  + (size_t)(e * 18 + cc) * 4096;
#pragma unroll
            for (int k = 0; k < 4; ++k) {
                int i = tid + k * 256;
                cp16s(sb + WB + bf * 16384 + i * 16, srcH + i * 4);
                cp16s(sb + WB + 32768 + bf * 16384 + i * 16, srcL + i * 4);
            }
            CP_COMMIT();
        };

        loadW(0, 0);
        loadW(1, 1);
#pragma unroll
        for (int f = 0; f < 8; f++)
#pragma unroll
            for (int i = 0; i < 4; i++) acc[f][i] = 0.f;

        // ---- GEMM1: 18 chunks of 64k ----
        for (int cc = 0; cc < 18; ++cc) {
            if (cc == 17) { CP_WAIT0(); } else { CP_WAIT1(); }
            __syncthreads();
            const int bf = cc & 1;
            const int j = cc >> 1;
            const int ky = j / 3, kx = j - 3 * (j / 3);
            const int R0 = ky * 66 + kx + wq * 16;
            const int h = cc & 1;
            const uint32_t whb = sb + WB + bf * 16384;          // fp16 W
            const uint32_t wlb = whb + 32768;                    // bf16 residual W
#pragma unroll
            for (int ks = 0; ks < 4; ++ks) {
                const int ci0 = h * 64 + ks * 16;
                uint32_t ah0, ah1, ah2, ah3, al0, al1, al2, al3;
                ldsm4(amat_addr(sb + SXH, R0, ci0, lane), ah0, ah1, ah2, ah3);
                ldsm4(amat_addr(sb + SXL, R0, ci0, lane), al0, al1, al2, al3);
#pragma unroll
                for (int nn = 0; nn < 4; ++nn) {
                    const int co0 = wh * 64 + nn * 16;
                    uint32_t bh0, bh1, bh2, bh3, bl0, bl1, bl2, bl3;
                    ldsm4t(amat_addr(whb, ks * 16, co0, lane), bh0, bh1, bh2, bh3);
                    ldsm4t(amat_addr(wlb, ks * 16, co0, lane), bl0, bl1, bl2, bl3);
                    float* d0 = acc[nn * 2];
                    float* d1 = acc[nn * 2 + 1];
                    mma_fp(d0, ah0, ah1, ah2, ah3, bh0, bh1);
                    mma_bf(d0, al0, al1, al2, al3, bl0, bl1);
                    mma_fp(d1, ah0, ah1, ah2, ah3, bh2, bh3);
                    mma_bf(d1, al0, al1, al2, al3, bl2, bl3);
                }
            }
            __syncthreads();
            if (cc + 2 < 18) loadW(cc + 2, bf);
        }

        // issue W_proj copies (hidden under squash epilogue)
        {
            const uint32_t* sH = g_wp_f16 + (size_t)e * 8192;
            const uint32_t* sL = g_wp_bf  + (size_t)e * 8192;
#pragma unroll
            for (int k = 0; k < 8; ++k) {
                int i = tid + k * 256;
                cp16s(sb + WB + i * 16, sH + i * 4);
                cp16s(sb + WB + 32768 + i * 16, sL + i * 4);
            }
            CP_COMMIT();
        }

        // ---- epilogue: bias + sum of squares ----
        float s0 = 0.f, s1 = 0.f;
#pragma unroll
        for (int f = 0; f < 8; ++f) {
            int co = wh * 64 + f * 8 + t4 * 2;
            float bc0 = __ldg(&bc_all[e * CC + co]);
            float bc1 = __ldg(&bc_all[e * CC + co + 1]);
            acc[f][0] += bc0; acc[f][1] += bc1;
            acc[f][2] += bc0; acc[f][3] += bc1;
            s0 = fmaf(acc[f][0], acc[f][0], s0); s0 = fmaf(acc[f][1], acc[f][1], s0);
            s1 = fmaf(acc[f][2], acc[f][2], s1); s1 = fmaf(acc[f][3], acc[f][3], s1);
        }
        s0 += __shfl_xor_sync(0xffffffffu, s0, 1);
        s0 += __shfl_xor_sync(0xffffffffu, s0, 2);
        s1 += __shfl_xor_sync(0xffffffffu, s1, 1);
        s1 += __shfl_xor_sync(0xffffffffu, s1, 2);
        if (t4 == 0) {
            spart[wh * 64 + wq * 16 + gq] = s0;
            spart[wh * 64 + wq * 16 + gq + 8] = s1;
        }
        __syncthreads();
        if (tid < 64) {
            float sn = spart[tid] + spart[64 + tid];
            ssc[tid] = sn / (1.f + sn) / (sqrtf(sn) + 1e-8f);
        }
        __syncthreads();
        // scale + store u (fp16 hi + bf16 residual; row = px)
        {
            int px0 = wq * 16 + gq, px1 = px0 + 8;
            float sc0 = ssc[px0], sc1 = ssc[px1];
#pragma unroll
            for (int f = 0; f < 8; ++f) {
                int co = wh * 64 + f * 8 + t4 * 2;
                uint32_t hi, lo;
                splitFB(acc[f][0] * sc0, acc[f][1] * sc0, hi, lo);
                uint32_t off0 = px0 * 256 + ((co * 2) ^ ((px0 & 7) << 4));
                *(uint32_t*)(smem + UTH + off0) = hi;
                *(uint32_t*)(smem + UTL + off0) = lo;
                splitFB(acc[f][2] * sc1, acc[f][3] * sc1, hi, lo);
                uint32_t off1 = px1 * 256 + ((co * 2) ^ ((px1 & 7) << 4));
                *(uint32_t*)(smem + UTH + off1) = hi;
                *(uint32_t*)(smem + UTL + off1) = lo;
            }
        }
        CP_WAIT0();
        __syncthreads();

        // ---- GEMM2: K=128 ----
#pragma unroll
        for (int f = 0; f < 8; f++)
#pragma unroll
            for (int i = 0; i < 4; i++) acc[f][i] = 0.f;
#pragma unroll
        for (int ks = 0; ks < 8; ++ks) {
            int kg = ks * 16;
            int bf2 = kg >> 6, kr = kg & 63;
            uint32_t whb = sb + WB + bf2 * 16384;
            uint32_t wlb = whb + 32768;
            uint32_t ah0, ah1, ah2, ah3, al0, al1, al2, al3;
            ldsm4(amat_addr(sb + UTH, wq * 16, kg, lane), ah0, ah1, ah2, ah3);
            ldsm4(amat_addr(sb + UTL, wq * 16, kg, lane), al0, al1, al2, al3);
#pragma unroll
            for (int nn = 0; nn < 4; ++nn) {
                int co0 = wh * 64 + nn * 16;
                uint32_t bh0, bh1, bh2, bh3, bl0, bl1, bl2, bl3;
                ldsm4t(amat_addr(whb, kr, co0, lane), bh0, bh1, bh2, bh3);
                ldsm4t(amat_addr(wlb, kr, co0, lane), bl0, bl1, bl2, bl3);
                float* d0 = acc[nn * 2];
                float* d1 = acc[nn * 2 + 1];
                mma_fp(d0, ah0, ah1, ah2, ah3, bh0, bh1);
                mma_bf(d0, al0, al1, al2, al3, bl0, bl1);
                mma_fp(d1, ah0, ah1, ah2, ah3, bh2, bh3);
                mma_bf(d1, al0, al1, al2, al3, bl2, bl3);
            }
        }
        // bias + 4-gate weighted accumulation
#pragma unroll
        for (int f = 0; f < 8; ++f) {
            int co = wh * 64 + f * 8 + t4 * 2;
            float bp0 = __ldg(&bp_all[e * CC + co]);
            float bp1 = __ldg(&bp_all[e * CC + co + 1]);
            float v0 = acc[f][0] + bp0, v1 = acc[f][1] + bp1;
            float v2 = acc[f][2] + bp0, v3 = acc[f][3] + bp1;
            yreg[0][f][0] = fmaf(wg0, v0, yreg[0][f][0]); yreg[0][f][1] = fmaf(wg0, v1, yreg[0][f][1]);
            yreg[0][f][2] = fmaf(wg0, v2, yreg[0][f][2]); yreg[0][f][3] = fmaf(wg0, v3, yreg[0][f][3]);
            yreg[1][f][0] = fmaf(wg1, v0, yreg[1][f][0]); yreg[1][f][1] = fmaf(wg1, v1, yreg[1][f][1]);
            yreg[1][f][2] = fmaf(wg1, v2, yreg[1][f][2]); yreg[1][f][3] = fmaf(wg1, v3, yreg[1][f][3]);
            yreg[2][f][0] = fmaf(wg2, v0, yreg[2][f][0]); yreg[2][f][1] = fmaf(wg2, v1, yreg[2][f][1]);
            yreg[2][f][2] = fmaf(wg2, v2, yreg[2][f][2]); yreg[2][f][3] = fmaf(wg2, v3, yreg[2][f][3]);
            yreg[3][f][0] = fmaf(wg3, v0, yreg[3][f][0]); yreg[3][f][1] = fmaf(wg3, v1, yreg[3][f][1]);
            yreg[3][f][2] = fmaf(wg3, v2, yreg[3][f][2]); yreg[3][f][3] = fmaf(wg3, v3, yreg[3][f][3]);
        }
    }

    // ---- final store: stage each gate through smem for coalesced STG.128 ----
    float* stage = (float*)(smem + WB);
    int px0 = wq * 16 + gq, px1 = px0 + 8;
#pragma unroll 1
    for (int g = 0; g < NG; ++g) {
        __syncthreads();
#pragma unroll
        for (int f = 0; f < 8; ++f) {
            int co = wh * 64 + f * 8 + t4 * 2;
            stage[co * 68 + px0]       = yreg[g][f][0];
            stage[(co + 1) * 68 + px0] = yreg[g][f][1];
            stage[co * 68 + px1]       = yreg[g][f][2];
            stage[(co + 1) * 68 + px1] = yreg[g][f][3];
        }
        __syncthreads();
        float* og = out + (size_t)g * YSZ + (size_t)b * IMG + (size_t)row * 64;
        int p4 = (tid & 15) * 4;
#pragma unroll
        for (int it = 0; it < 8; ++it) {
            int co = (tid >> 4) + it * 16;
            float4 v = *(float4*)&stage[co * 68 + p4];
            *(float4*)&og[(size_t)co * HWPIX + p4] = v;
        }
    }
}

// ---------------------------------------------------------------------------
extern "C" void kernel_launch(void* const* d_in, const int* in_sizes, int n_in,
                              void* d_out, int out_size) {
    const float* x  = (const float*)d_in[0];
    const float* g1 = (const float*)d_in[1];
    const float* g2 = (const float*)d_in[2];
    const float* g3 = (const float*)d_in[3];
    const float* g4 = (const float*)d_in[4];
    const float* Wc = (const float*)d_in[5];
    const float* bc = (const float*)d_in[6];
    const float* Wp = (const float*)d_in[7];
    const float* bp = (const float*)d_in[8];
    float* out = (float*)d_out;

    cudaFuncSetAttribute(moe_main, cudaFuncAttributeMaxDynamicSharedMemorySize, SMEM_BYTES);

    mean_kernel<<<BB * CC, 256>>>(x);
    gate_kernel<<<1, 32>>>(g1, g2, g3, g4, out + (out_size - 1));
    prep_wc<<<EE * 18, 256>>>(Wc);
    prep_wp<<<EE * 2, 256>>>(Wp);
    moe_main<<<512, 256, SMEM_BYTES>>>(x, bc, bp, out);
}

// round 10
// speedup vs baseline: 6.3633x; 1.1009x over previous
#include <cuda_runtime.h>
#include <cuda_bf16.h>
#include <cuda_fp16.h>
#include <cstdint>

#define CC   128
#define BB   8
#define EE   8
#define NG   4
#define HWPIX 4096
#define IMG  524288   // 128*64*64
#define YSZ  4194304  // 8*128*64*64
#define NBLK 256      // 8 b x 32 row-pairs

__device__ float g_x0[BB * CC];
__device__ float g_w[NG * BB * EE];

// Pre-converted weights (swizzled 16KB chunk images)
__device__ uint32_t g_wc_f16[EE * 18 * 4096];
__device__ uint32_t g_wc_bf [EE * 18 * 4096];
__device__ uint32_t g_wp_f16[EE * 2 * 4096];
__device__ uint32_t g_wp_bf [EE * 2 * 4096];
// per-expert v staging: [e][blk][co][px]
__device__ float g_scr[(size_t)EE * NBLK * 16384];

// ---------------------------------------------------------------------------
__global__ void mean_kernel(const float* __restrict__ x) {
    int bc = blockIdx.x;
    const float4* p = (const float4*)(x + (size_t)bc * HWPIX);
    float s = 0.f;
    for (int i = threadIdx.x; i < 1024; i += 256) { float4 v = p[i]; s += (v.x + v.y) + (v.z + v.w); }
    for (int o = 16; o; o >>= 1) s += __shfl_xor_sync(0xffffffffu, s, o);
    __shared__ float sm[8];
    if ((threadIdx.x & 31) == 0) sm[threadIdx.x >> 5] = s;
    __syncthreads();
    if (threadIdx.x < 8) {
        float v = sm[threadIdx.x];
        for (int o = 4; o; o >>= 1) v += __shfl_xor_sync(0xffu, v, o);
        if (threadIdx.x == 0) g_x0[bc] = v * (1.0f / 4096.0f);
    }
}

__global__ void gate_kernel(const float* __restrict__ g1, const float* __restrict__ g2,
                            const float* __restrict__ g3, const float* __restrict__ g4,
                            float* __restrict__ loss_out) {
    int lane = threadIdx.x;
    int g = lane >> 3, b = lane & 7;
    const float* G = (g == 0) ? g1 : (g == 1) ? g2 : (g == 2) ? g3 : g4;
    const float* x0 = &g_x0[b * CC];
    float lg[8];
#pragma unroll
    for (int e = 0; e < 8; e++) lg[e] = 0.f;
    for (int c = 0; c < CC; c++) {
        float xv = x0[c];
#pragma unroll
        for (int e = 0; e < 8; e++) lg[e] += xv * G[c * 8 + e];
    }
    float m = lg[0];
#pragma unroll
    for (int e = 1; e < 8; e++) m = fmaxf(m, lg[e]);
    float p[8], sum = 0.f;
#pragma unroll
    for (int e = 0; e < 8; e++) { p[e] = expf(lg[e] - m); sum += p[e]; }
    float inv = 1.f / sum;
#pragma unroll
    for (int e = 0; e < 8; e++) p[e] *= inv;
    int i1 = 0;
#pragma unroll
    for (int e = 1; e < 8; e++) if (p[e] > p[i1]) i1 = e;
    int i2 = (i1 == 0) ? 1 : 0;
#pragma unroll
    for (int e = 0; e < 8; e++) { if (e == i1 || e == i2) continue; if (p[e] > p[i2]) i2 = e; }
    float m2 = fmaxf(p[i1], p[i2]);
    float e1 = expf(p[i1] - m2), e2 = expf(p[i2] - m2);
    float winv = 1.f / (e1 + e2);
    float* wrow = &g_w[(g * 8 + b) * 8];
#pragma unroll
    for (int e = 0; e < 8; e++) wrow[e] = 0.f;
    wrow[i1] = e1 * winv;
    wrow[i2] = e2 * winv;
    float u[8];
#pragma unroll
    for (int e = 0; e < 8; e++) {
        u[e] = p[e];
        for (int o = 1; o < 8; o <<= 1) u[e] += __shfl_xor_sync(0xffffffffu, u[e], o);
    }
    __shared__ float sl[4];
    if (b == 0) {
        float mu = 0.f;
#pragma unroll
        for (int e = 0; e < 8; e++) mu += u[e];
        mu *= (1.0f / 8.0f);
        float var = 0.f;
#pragma unroll
        for (int e = 0; e < 8; e++) { float d = u[e] - mu; var += d * d; }
        var *= (1.0f / 7.0f);
        sl[g] = var / (mu * mu + 1e-10f);
    }
    __syncwarp();
    if (lane == 0) loss_out[0] = sl[0] + sl[1] + sl[2] + sl[3];
}

// split: (fp16 hi pair, bf16 residual pair)
__device__ __forceinline__ void splitFB(float v0, float v1, uint32_t& hi, uint32_t& lo) {
    __half h0 = __float2half_rn(v0), h1 = __float2half_rn(v1);
    float f0 = __half2float(h0), f1 = __half2float(h1);
    __nv_bfloat16 l0 = __float2bfloat16(v0 - f0), l1 = __float2bfloat16(v1 - f1);
    __half2 ph; ph.x = h0; ph.y = h1;
    __nv_bfloat162 pl; pl.x = l0; pl.y = l1;
    hi = *(uint32_t*)&ph;
    lo = *(uint32_t*)&pl;
}

__global__ void prep_wc(const float* __restrict__ Wc_all) {
    int e = blockIdx.x / 18, cc = blockIdx.x % 18;
    int j = cc >> 1, h = cc & 1;
    const float* Wc = Wc_all + (size_t)e * (CC * 1152);
    uint32_t* oh = g_wc_f16 + (size_t)blockIdx.x * 4096;
    uint32_t* ol = g_wc_bf  + (size_t)blockIdx.x * 4096;
#pragma unroll 4
    for (int idx = threadIdx.x; idx < 4096; idx += 256) {
        int r = idx >> 6, cop = idx & 63;
        int co = cop * 2, ci = h * 64 + r;
        float v0 = __ldg(Wc + (size_t)co * 1152 + ci * 9 + j);
        float v1 = __ldg(Wc + (size_t)(co + 1) * 1152 + ci * 9 + j);
        uint32_t hi, lo;
        splitFB(v0, v1, hi, lo);
        uint32_t woff = (r * 256 + ((co * 2) ^ ((r & 7) << 4))) >> 2;
        oh[woff] = hi;
        ol[woff] = lo;
    }
}

__global__ void prep_wp(const float* __restrict__ Wp_all) {
    int e = blockIdx.x >> 1, bf2 = blockIdx.x & 1;
    const float* Wp = Wp_all + (size_t)e * 16384;
    uint32_t* oh = g_wp_f16 + (size_t)blockIdx.x * 4096;
    uint32_t* ol = g_wp_bf  + (size_t)blockIdx.x * 4096;
#pragma unroll 4
    for (int idx = threadIdx.x; idx < 4096; idx += 256) {
        int r = idx >> 6, cop = idx & 63;
        int co = cop * 2, ci = bf2 * 64 + r;
        float v0 = __ldg(Wp + (size_t)co * 128 + ci);
        float v1 = __ldg(Wp + (size_t)(co + 1) * 128 + ci);
        uint32_t hi, lo;
        splitFB(v0, v1, hi, lo);
        uint32_t woff = (r * 256 + ((co * 2) ^ ((r & 7) << 4))) >> 2;
        oh[woff] = hi;
        ol[woff] = lo;
    }
}

// dummy kernel: aligns ncu's -s 5 -c 1 capture onto moe_main (6th launch)
__global__ void noop_kernel(float* p) { if (threadIdx.x == 1024) p[0] = 0.f; }

// ---------------------------------------------------------------------------
// Main kernel (round 10): 128px block (2 output rows), warp tile 32px x 64co.
// ---------------------------------------------------------------------------

#define SXH   0                    // x fp16 hi: 264 rows x 256B
#define SXL   67584                // x bf16 residual
#define WOFF  135168               // 64KB multi-use region
#define SWG   200704
#define SPARTB 200832              // 2 x 128 floats
#define SSCB  201856               // 128 floats
#define SMEM_BYTES 202368

__device__ __forceinline__ void ldsm4(uint32_t a, uint32_t& r0, uint32_t& r1,
                                      uint32_t& r2, uint32_t& r3) {
    asm volatile("ldmatrix.sync.aligned.m8n8.x4.shared.b16 {%0,%1,%2,%3}, [%4];"
                 : "=r"(r0), "=r"(r1), "=r"(r2), "=r"(r3) : "r"(a));
}
__device__ __forceinline__ void ldsm4t(uint32_t a, uint32_t& r0, uint32_t& r1,
                                       uint32_t& r2, uint32_t& r3) {
    asm volatile("ldmatrix.sync.aligned.m8n8.x4.trans.shared.b16 {%0,%1,%2,%3}, [%4];"
                 : "=r"(r0), "=r"(r1), "=r"(r2), "=r"(r3) : "r"(a));
}
__device__ __forceinline__ void mma_bf(float* d, const uint32_t* a,
                                       uint32_t b0, uint32_t b1) {
    asm volatile(
        "mma.sync.aligned.m16n8k16.row.col.f32.bf16.bf16.f32 "
        "{%0,%1,%2,%3},{%4,%5,%6,%7},{%8,%9},{%0,%1,%2,%3};"
        : "+f"(d[0]), "+f"(d[1]), "+f"(d[2]), "+f"(d[3])
        : "r"(a[0]), "r"(a[1]), "r"(a[2]), "r"(a[3]), "r"(b0), "r"(b1));
}
__device__ __forceinline__ void mma_fp(float* d, const uint32_t* a,
                                       uint32_t b0, uint32_t b1) {
    asm volatile(
        "mma.sync.aligned.m16n8k16.row.col.f32.f16.f16.f32 "
        "{%0,%1,%2,%3},{%4,%5,%6,%7},{%8,%9},{%0,%1,%2,%3};"
        : "+f"(d[0]), "+f"(d[1]), "+f"(d[2]), "+f"(d[3])
        : "r"(a[0]), "r"(a[1]), "r"(a[2]), "r"(a[3]), "r"(b0), "r"(b1));
}
// 256B-row tables (x tiles, weight images)
__device__ __forceinline__ uint32_t amat_addr(uint32_t base, int R0, int ci0, int lane) {
    int sel = lane >> 3;
    int r = R0 + (lane & 7) + ((sel & 1) << 3);
    int cb = (ci0 + ((sel >> 1) << 3)) * 2;
    return base + r * 256 + (cb ^ ((r & 7) << 4));
}
// 128B-row tables (u half-tables)
__device__ __forceinline__ uint32_t amat128(uint32_t base, int R0, int k0, int lane) {
    int sel = lane >> 3;
    int r = R0 + (lane & 7) + ((sel & 1) << 3);
    int cb = (k0 + ((sel >> 1) << 3)) * 2;
    uint32_t sw = ((uint32_t)(cb & 0x70) ^ (uint32_t)((r & 7) << 4)) | (uint32_t)(cb & 0xF);
    return base + r * 128 + sw;
}
__device__ __forceinline__ uint32_t sw128b(int r, int cb) {
    return (uint32_t)(r * 128) + ((((uint32_t)cb & 0x70) ^ (uint32_t)((r & 7) << 4)) | ((uint32_t)cb & 0xF));
}
__device__ __forceinline__ void cp16s(uint32_t dst, const void* src) {
    asm volatile("cp.async.ca.shared.global [%0], [%1], 16;" :: "r"(dst), "l"(src));
}
#define CP_COMMIT() asm volatile("cp.async.commit_group;")
#define CP_WAIT1()  asm volatile("cp.async.wait_group 1;")
#define CP_WAIT0()  asm volatile("cp.async.wait_group 0;")

__global__ void __launch_bounds__(256, 1)
moe_main(const float* __restrict__ x,
         const float* __restrict__ bc_all, const float* __restrict__ bp_all,
         float* __restrict__ out) {
    extern __shared__ char smem[];
    const uint32_t sb = (uint32_t)__cvta_generic_to_shared(smem);
    float* swg   = (float*)(smem + SWG);
    float* spart = (float*)(smem + SPARTB);
    float* ssc   = (float*)(smem + SSCB);

    const int tid  = threadIdx.x;
    const int lane = tid & 31;
    const int warp = tid >> 5;
    const int wq = warp >> 1;          // px group of 32
    const int wh = warp & 1;           // co half
    const int blk  = blockIdx.x;
    const int b    = blk >> 5;
    const int row0 = (blk & 31) * 2;
    const int gq = lane >> 2, t4 = lane & 3;

    if (tid < 32) {
        int g = tid >> 3, e = tid & 7;
        swg[tid] = g_w[(g * 8 + b) * 8 + e];
    }

    // ---- x strip (4 halo rows, 66 cols, 128 ci): fp16 hi + bf16 residual ----
    {
        const float* xb = x + (size_t)b * IMG;
        for (int it = 0; it < 64; ++it) {
            int rid = warp + it * 8;          // 0..511 = gry*128 + ci
            int gry = rid >> 7, ci = rid & 127;
            int gr = row0 - 1 + gry;
#pragma unroll
            for (int cl = 0; cl < 3; ++cl) {
                int c = lane + cl * 32;
                if (cl == 2 && lane >= 2) break;
                int gc = c - 1;
                float v = 0.f;
                if ((unsigned)gr < 64u && (unsigned)gc < 64u)
                    v = xb[ci * HWPIX + gr * 64 + gc];
                __half h = __float2half_rn(v);
                __nv_bfloat16 l = __float2bfloat16(v - __half2float(h));
                int R = gry * 66 + c;
                uint32_t off = R * 256 + ((ci * 2) ^ ((R & 7) << 4));
                *(__half*)(smem + SXH + off) = h;
                *(__nv_bfloat16*)(smem + SXL + off) = l;
            }
        }
    }

    float acc[2][8][4];

    for (int e = 0; e < EE; ++e) {
        float we0 = swg[e], we1 = swg[8 + e], we2 = swg[16 + e], we3 = swg[24 + e];
        __syncthreads();
        if (we0 == 0.f && we1 == 0.f && we2 == 0.f && we3 == 0.f) continue;

        auto loadW = [&](int cc, int bf) {
            const uint32_t* srcH = g_wc_f16 + (size_t)(e * 18 + cc) * 4096;
            const uint32_t* srcL = g_wc_bf  + (size_t)(e * 18 + cc) * 4096;
#pragma unroll
            for (int k = 0; k < 4; ++k) {
                int i = tid + k * 256;
                cp16s(sb + WOFF + bf * 16384 + i * 16, srcH + i * 4);
                cp16s(sb + WOFF + 32768 + bf * 16384 + i * 16, srcL + i * 4);
            }
            CP_COMMIT();
        };

        loadW(0, 0);
        loadW(1, 1);
#pragma unroll
        for (int pm = 0; pm < 2; ++pm)
#pragma unroll
            for (int f = 0; f < 8; ++f)
#pragma unroll
                for (int i = 0; i < 4; ++i) acc[pm][f][i] = 0.f;

        // ---- GEMM1: 18 chunks of 64k ----
        for (int cc = 0; cc < 18; ++cc) {
            if (cc == 17) { CP_WAIT0(); } else { CP_WAIT1(); }
            __syncthreads();
            const int bf = cc & 1;
            const int j = cc >> 1;
            const int ky = j / 3, kx = j - 3 * (j / 3);
            const int h = cc & 1;
            const uint32_t whb = sb + WOFF + bf * 16384;
            const uint32_t wlb = whb + 32768;
#pragma unroll
            for (int ks = 0; ks < 4; ++ks) {
                const int ci0 = h * 64 + ks * 16;
                uint32_t ah[2][4], al[2][4];
#pragma unroll
                for (int pm = 0; pm < 2; ++pm) {
                    int P0 = wq * 32 + pm * 16;
                    int R0 = ((P0 >> 6) + ky) * 66 + (P0 & 63) + kx;
                    ldsm4(amat_addr(sb + SXH, R0, ci0, lane), ah[pm][0], ah[pm][1], ah[pm][2], ah[pm][3]);
                    ldsm4(amat_addr(sb + SXL, R0, ci0, lane), al[pm][0], al[pm][1], al[pm][2], al[pm][3]);
                }
#pragma unroll
                for (int nn = 0; nn < 4; ++nn) {
                    const int co0 = wh * 64 + nn * 16;
                    uint32_t bh0, bh1, bh2, bh3, bl0, bl1, bl2, bl3;
                    ldsm4t(amat_addr(whb, ks * 16, co0, lane), bh0, bh1, bh2, bh3);
                    ldsm4t(amat_addr(wlb, ks * 16, co0, lane), bl0, bl1, bl2, bl3);
#pragma unroll
                    for (int pm = 0; pm < 2; ++pm) {
                        mma_fp(acc[pm][nn * 2], ah[pm], bh0, bh1);
                        mma_bf(acc[pm][nn * 2], al[pm], bl0, bl1);
                        mma_fp(acc[pm][nn * 2 + 1], ah[pm], bh2, bh3);
                        mma_bf(acc[pm][nn * 2 + 1], al[pm], bl2, bl3);
                    }
                }
            }
            __syncthreads();
            if (cc + 2 < 18) loadW(cc + 2, bf);
        }

        // ---- bias + per-pixel sum of squares ----
#pragma unroll
        for (int pm = 0; pm < 2; ++pm) {
            float sa = 0.f, sb2 = 0.f;
#pragma unroll
            for (int f = 0; f < 8; ++f) {
                int co = wh * 64 + f * 8 + t4 * 2;
                float bc0 = __ldg(&bc_all[e * CC + co]);
                float bc1 = __ldg(&bc_all[e * CC + co + 1]);
                acc[pm][f][0] += bc0; acc[pm][f][1] += bc1;
                acc[pm][f][2] += bc0; acc[pm][f][3] += bc1;
                sa = fmaf(acc[pm][f][0], acc[pm][f][0], sa);
                sa = fmaf(acc[pm][f][1], acc[pm][f][1], sa);
                sb2 = fmaf(acc[pm][f][2], acc[pm][f][2], sb2);
                sb2 = fmaf(acc[pm][f][3], acc[pm][f][3], sb2);
            }
            sa += __shfl_xor_sync(0xffffffffu, sa, 1);
            sa += __shfl_xor_sync(0xffffffffu, sa, 2);
            sb2 += __shfl_xor_sync(0xffffffffu, sb2, 1);
            sb2 += __shfl_xor_sync(0xffffffffu, sb2, 2);
            if (t4 == 0) {
                int pxa = wq * 32 + pm * 16 + gq;
                spart[wh * 128 + pxa] = sa;
                spart[wh * 128 + pxa + 8] = sb2;
            }
        }
        __syncthreads();
        if (tid < 128) {
            float sn = spart[tid] + spart[128 + tid];
            ssc[tid] = sn / (1.f + sn) / (sqrtf(sn) + 1e-8f);
        }
        __syncthreads();
        // scale (acc becomes u)
#pragma unroll
        for (int pm = 0; pm < 2; ++pm) {
            int pxa = wq * 32 + pm * 16 + gq;
            float s0 = ssc[pxa], s1 = ssc[pxa + 8];
#pragma unroll
            for (int f = 0; f < 8; ++f) {
                acc[pm][f][0] *= s0; acc[pm][f][1] *= s0;
                acc[pm][f][2] *= s1; acc[pm][f][3] *= s1;
            }
        }

        // ---- GEMM2 in two ci-halves through the freed W region ----
        float acc2[2][8][4];
#pragma unroll
        for (int pm = 0; pm < 2; ++pm)
#pragma unroll
            for (int f = 0; f < 8; ++f)
#pragma unroll
                for (int i = 0; i < 4; ++i) acc2[pm][f][i] = 0.f;

        for (int h2 = 0; h2 < 2; ++h2) {
            if (wh == h2) {
                // stage u half: rows=px (128 x 128B), swizzled
#pragma unroll
                for (int pm = 0; pm < 2; ++pm) {
                    int pxa = wq * 32 + pm * 16 + gq;
                    int cb = (/*co_local*/ t4 * 2) * 2;   // completed per f below
#pragma unroll
                    for (int f = 0; f < 8; ++f) {
                        int cl2 = (f * 8 + t4 * 2) * 2;    // byte col
                        uint32_t hi, lo;
                        splitFB(acc[pm][f][0], acc[pm][f][1], hi, lo);
                        uint32_t o0 = sw128b(pxa, cl2);
                        *(uint32_t*)(smem + WOFF + o0) = hi;
                        *(uint32_t*)(smem + WOFF + 16384 + o0) = lo;
                        splitFB(acc[pm][f][2], acc[pm][f][3], hi, lo);
                        uint32_t o1 = sw128b(pxa + 8, cl2);
                        *(uint32_t*)(smem + WOFF + o1) = hi;
                        *(uint32_t*)(smem + WOFF + 16384 + o1) = lo;
                    }
                    (void)cb;
                }
            }
            // cp.async W_proj half images
            {
                const uint32_t* pH = g_wp_f16 + (size_t)(e * 2 + h2) * 4096;
                const uint32_t* pL = g_wp_bf  + (size_t)(e * 2 + h2) * 4096;
#pragma unroll
                for (int k = 0; k < 4; ++k) {
                    int i = tid + k * 256;
                    cp16s(sb + WOFF + 32768 + i * 16, pH + i * 4);
                    cp16s(sb + WOFF + 49152 + i * 16, pL + i * 4);
                }
                CP_COMMIT();
                CP_WAIT0();
            }
            __syncthreads();
#pragma unroll
            for (int ks = 0; ks < 4; ++ks) {
                uint32_t ah[2][4], al[2][4];
#pragma unroll
                for (int pm = 0; pm < 2; ++pm) {
                    int R0 = wq * 32 + pm * 16;
                    ldsm4(amat128(sb + WOFF, R0, ks * 16, lane), ah[pm][0], ah[pm][1], ah[pm][2], ah[pm][3]);
                    ldsm4(amat128(sb + WOFF + 16384, R0, ks * 16, lane), al[pm][0], al[pm][1], al[pm][2], al[pm][3]);
                }
#pragma unroll
                for (int nn = 0; nn < 4; ++nn) {
                    int co0 = wh * 64 + nn * 16;
                    uint32_t bh0, bh1, bh2, bh3, bl0, bl1, bl2, bl3;
                    ldsm4t(amat_addr(sb + WOFF + 32768, ks * 16, co0, lane), bh0, bh1, bh2, bh3);
                    ldsm4t(amat_addr(sb + WOFF + 49152, ks * 16, co0, lane), bl0, bl1, bl2, bl3);
#pragma unroll
                    for (int pm = 0; pm < 2; ++pm) {
                        mma_fp(acc2[pm][nn * 2], ah[pm], bh0, bh1);
                        mma_bf(acc2[pm][nn * 2], al[pm], bl0, bl1);
                        mma_fp(acc2[pm][nn * 2 + 1], ah[pm], bh2, bh3);
                        mma_bf(acc2[pm][nn * 2 + 1], al[pm], bl2, bl3);
                    }
                }
            }
            __syncthreads();
        }

        // ---- v = acc2 + bp -> scratch (staged for coalesced writes) ----
        float* stg = (float*)(smem + WOFF);   // [64 co][132]
        for (int r = 0; r < 2; ++r) {
            if (wh == r) {
#pragma unroll
                for (int pm = 0; pm < 2; ++pm) {
                    int pxa = wq * 32 + pm * 16 + gq;
#pragma unroll
                    for (int f = 0; f < 8; ++f) {
                        int cl = f * 8 + t4 * 2;
                        float bp0 = __ldg(&bp_all[e * CC + r * 64 + cl]);
                        float bp1 = __ldg(&bp_all[e * CC + r * 64 + cl + 1]);
                        stg[cl * 132 + pxa]         = acc2[pm][f][0] + bp0;
                        stg[(cl + 1) * 132 + pxa]   = acc2[pm][f][1] + bp1;
                        stg[cl * 132 + pxa + 8]     = acc2[pm][f][2] + bp0;
                        stg[(cl + 1) * 132 + pxa + 8] = acc2[pm][f][3] + bp1;
                    }
                }
            }
            __syncthreads();
            float* dst = g_scr + (size_t)(e * NBLK + blk) * 16384 + r * 64 * 128;
#pragma unroll
            for (int k = 0; k < 8; ++k) {
                int i = tid + k * 256;
                int cl = i >> 5, p4 = (i & 31) * 4;
                float4 v = *(float4*)&stg[cl * 132 + p4];
                *(float4*)&dst[cl * 128 + p4] = v;
            }
            __syncthreads();
        }
    }

    // ---- combine: y_g = sum_e w_ge * v_e ----
    __threadfence_block();
    __syncthreads();
#pragma unroll 1
    for (int k = 0; k < 16; ++k) {
        int i = tid + k * 256;                 // 0..4095 float4 ids
        int co = i >> 5, p4 = (i & 31) * 4;
        float4 y0 = {0, 0, 0, 0}, y1 = y0, y2 = y0, y3 = y0;
#pragma unroll
        for (int e = 0; e < EE; ++e) {
            float a0 = swg[e], a1 = swg[8 + e], a2 = swg[16 + e], a3 = swg[24 + e];
            if (a0 == 0.f && a1 == 0.f && a2 == 0.f && a3 == 0.f) continue;
            float4 v = *(const float4*)(g_scr + (size_t)(e * NBLK + blk) * 16384 + co * 128 + p4);
            y0.x += a0 * v.x; y0.y += a0 * v.y; y0.z += a0 * v.z; y0.w += a0 * v.w;
            y1.x += a1 * v.x; y1.y += a1 * v.y; y1.z += a1 * v.z; y1.w += a1 * v.w;
            y2.x += a2 * v.x; y2.y += a2 * v.y; y2.z += a2 * v.z; y2.w += a2 * v.w;
            y3.x += a3 * v.x; y3.y += a3 * v.y; y3.z += a3 * v.z; y3.w += a3 * v.w;
        }
        int r2 = p4 >> 6, col = p4 & 63;
        size_t gidx = (size_t)b * IMG + (size_t)co * HWPIX + (size_t)(row0 + r2) * 64 + col;
        *(float4*)(out + gidx) = y0;
        *(float4*)(out + YSZ + gidx) = y1;
        *(float4*)(out + 2 * YSZ + gidx) = y2;
        *(float4*)(out + 3 * YSZ + gidx) = y3;
    }
}

// ---------------------------------------------------------------------------
extern "C" void kernel_launch(void* const* d_in, const int* in_sizes, int n_in,
                              void* d_out, int out_size) {
    const float* x  = (const float*)d_in[0];
    const float* g1 = (const float*)d_in[1];
    const float* g2 = (const float*)d_in[2];
    const float* g3 = (const float*)d_in[3];
    const float* g4 = (const float*)d_in[4];
    const float* Wc = (const float*)d_in[5];
    const float* bc = (const float*)d_in[6];
    const float* Wp = (const float*)d_in[7];
    const float* bp = (const float*)d_in[8];
    float* out = (float*)d_out;

    cudaFuncSetAttribute(moe_main, cudaFuncAttributeMaxDynamicSharedMemorySize, SMEM_BYTES);

    mean_kernel<<<BB * CC, 256>>>(x);
    gate_kernel<<<1, 32>>>(g1, g2, g3, g4, out + (out_size - 1));
    prep_wc<<<EE * 18, 256>>>(Wc);
    prep_wp<<<EE * 2, 256>>>(Wp);
    noop_kernel<<<1, 32>>>(out);               // ncu -s 5 alignment: moe_main is launch #6
    moe_main<<<NBLK, 256, SMEM_BYTES>>>(x, bc, bp, out);
}

// round 11
// speedup vs baseline: 10.4044x; 1.6351x over previous
#include <cuda_runtime.h>
#include <cuda_bf16.h>
#include <cuda_fp16.h>
#include <cstdint>

#define CC   128
#define BB   8
#define EE   8
#define NG   4
#define HWPIX 4096
#define IMG  524288   // 128*64*64
#define YSZ  4194304  // 8*128*64*64
#define NBLK 256      // 8 b x 32 row-pairs

__device__ float g_x0[BB * CC];
__device__ float g_w[NG * BB * EE];

// Pre-converted fp16 weights (swizzled 16KB chunk images)
__device__ uint32_t g_wc_f16[EE * 18 * 4096];
__device__ uint32_t g_wp_f16[EE * 2 * 4096];
// per-expert v staging: [e][blk][co][px]
__device__ float g_scr[(size_t)EE * NBLK * 16384];

// ---------------------------------------------------------------------------
__global__ void mean_kernel(const float* __restrict__ x) {
    int bc = blockIdx.x;
    const float4* p = (const float4*)(x + (size_t)bc * HWPIX);
    float s = 0.f;
    for (int i = threadIdx.x; i < 1024; i += 256) { float4 v = p[i]; s += (v.x + v.y) + (v.z + v.w); }
    for (int o = 16; o; o >>= 1) s += __shfl_xor_sync(0xffffffffu, s, o);
    __shared__ float sm[8];
    if ((threadIdx.x & 31) == 0) sm[threadIdx.x >> 5] = s;
    __syncthreads();
    if (threadIdx.x < 8) {
        float v = sm[threadIdx.x];
        for (int o = 4; o; o >>= 1) v += __shfl_xor_sync(0xffu, v, o);
        if (threadIdx.x == 0) g_x0[bc] = v * (1.0f / 4096.0f);
    }
}

__global__ void gate_kernel(const float* __restrict__ g1, const float* __restrict__ g2,
                            const float* __restrict__ g3, const float* __restrict__ g4,
                            float* __restrict__ loss_out) {
    int lane = threadIdx.x;
    int g = lane >> 3, b = lane & 7;
    const float* G = (g == 0) ? g1 : (g == 1) ? g2 : (g == 2) ? g3 : g4;
    const float* x0 = &g_x0[b * CC];
    float lg[8];
#pragma unroll
    for (int e = 0; e < 8; e++) lg[e] = 0.f;
    for (int c = 0; c < CC; c++) {
        float xv = x0[c];
#pragma unroll
        for (int e = 0; e < 8; e++) lg[e] += xv * G[c * 8 + e];
    }
    float m = lg[0];
#pragma unroll
    for (int e = 1; e < 8; e++) m = fmaxf(m, lg[e]);
    float p[8], sum = 0.f;
#pragma unroll
    for (int e = 0; e < 8; e++) { p[e] = expf(lg[e] - m); sum += p[e]; }
    float inv = 1.f / sum;
#pragma unroll
    for (int e = 0; e < 8; e++) p[e] *= inv;
    int i1 = 0;
#pragma unroll
    for (int e = 1; e < 8; e++) if (p[e] > p[i1]) i1 = e;
    int i2 = (i1 == 0) ? 1 : 0;
#pragma unroll
    for (int e = 0; e < 8; e++) { if (e == i1 || e == i2) continue; if (p[e] > p[i2]) i2 = e; }
    float m2 = fmaxf(p[i1], p[i2]);
    float e1 = expf(p[i1] - m2), e2 = expf(p[i2] - m2);
    float winv = 1.f / (e1 + e2);
    float* wrow = &g_w[(g * 8 + b) * 8];
#pragma unroll
    for (int e = 0; e < 8; e++) wrow[e] = 0.f;
    wrow[i1] = e1 * winv;
    wrow[i2] = e2 * winv;
    float u[8];
#pragma unroll
    for (int e = 0; e < 8; e++) {
        u[e] = p[e];
        for (int o = 1; o < 8; o <<= 1) u[e] += __shfl_xor_sync(0xffffffffu, u[e], o);
    }
    __shared__ float sl[4];
    if (b == 0) {
        float mu = 0.f;
#pragma unroll
        for (int e = 0; e < 8; e++) mu += u[e];
        mu *= (1.0f / 8.0f);
        float var = 0.f;
#pragma unroll
        for (int e = 0; e < 8; e++) { float d = u[e] - mu; var += d * d; }
        var *= (1.0f / 7.0f);
        sl[g] = var / (mu * mu + 1e-10f);
    }
    __syncwarp();
    if (lane == 0) loss_out[0] = sl[0] + sl[1] + sl[2] + sl[3];
}

__device__ __forceinline__ uint32_t packh2(float a, float b) {
    __half2 h; h.x = __float2half_rn(a); h.y = __float2half_rn(b);
    return *(uint32_t*)&h;
}

// W_caps -> fp16 swizzled 16KB chunk images. chunk cc = tap j*2 + ci-half h.
// Row r = ci within half (0..63), 128 co (2B) per row, swizzled.
__global__ void prep_wc(const float* __restrict__ Wc_all) {
    int e = blockIdx.x / 18, cc = blockIdx.x % 18;
    int j = cc >> 1, h = cc & 1;
    const float* Wc = Wc_all + (size_t)e * (CC * 1152);
    uint32_t* oh = g_wc_f16 + (size_t)blockIdx.x * 4096;
#pragma unroll 4
    for (int idx = threadIdx.x; idx < 4096; idx += 256) {
        int r = idx >> 6, cop = idx & 63;
        int co = cop * 2, ci = h * 64 + r;
        float v0 = __ldg(Wc + (size_t)co * 1152 + ci * 9 + j);
        float v1 = __ldg(Wc + (size_t)(co + 1) * 1152 + ci * 9 + j);
        uint32_t woff = (r * 256 + ((co * 2) ^ ((r & 7) << 4))) >> 2;
        oh[woff] = packh2(v0, v1);
    }
}

__global__ void prep_wp(const float* __restrict__ Wp_all) {
    int e = blockIdx.x >> 1, h = blockIdx.x & 1;
    const float* Wp = Wp_all + (size_t)e * 16384;
    uint32_t* oh = g_wp_f16 + (size_t)blockIdx.x * 4096;
#pragma unroll 4
    for (int idx = threadIdx.x; idx < 4096; idx += 256) {
        int r = idx >> 6, cop = idx & 63;
        int co = cop * 2, ci = h * 64 + r;
        float v0 = __ldg(Wp + (size_t)co * 128 + ci);
        float v1 = __ldg(Wp + (size_t)(co + 1) * 128 + ci);
        uint32_t woff = (r * 256 + ((co * 2) ^ ((r & 7) << 4))) >> 2;
        oh[woff] = packh2(v0, v1);
    }
}

// ---------------------------------------------------------------------------
// Main kernel (round 11): pure fp16 mma. 128px block, warp tile 32px x 64co.
// Quad-buffered weight streaming (prefetch distance 3), 1 sync/chunk.
// ---------------------------------------------------------------------------

#define SXH   0                    // x fp16: 264 rows x 256B = 67584
#define WOFF  67584                // 4 x 16KB buffers (multi-use)
#define SWG   133120
#define SPARTB 133248              // 2 x 128 floats
#define SSCB  134272               // 128 floats
#define SMEM_BYTES 134784

__device__ __forceinline__ void ldsm4(uint32_t a, uint32_t& r0, uint32_t& r1,
                                      uint32_t& r2, uint32_t& r3) {
    asm volatile("ldmatrix.sync.aligned.m8n8.x4.shared.b16 {%0,%1,%2,%3}, [%4];"
                 : "=r"(r0), "=r"(r1), "=r"(r2), "=r"(r3) : "r"(a));
}
__device__ __forceinline__ void ldsm4t(uint32_t a, uint32_t& r0, uint32_t& r1,
                                       uint32_t& r2, uint32_t& r3) {
    asm volatile("ldmatrix.sync.aligned.m8n8.x4.trans.shared.b16 {%0,%1,%2,%3}, [%4];"
                 : "=r"(r0), "=r"(r1), "=r"(r2), "=r"(r3) : "r"(a));
}
__device__ __forceinline__ void mma_fp(float* d, const uint32_t* a,
                                       uint32_t b0, uint32_t b1) {
    asm volatile(
        "mma.sync.aligned.m16n8k16.row.col.f32.f16.f16.f32 "
        "{%0,%1,%2,%3},{%4,%5,%6,%7},{%8,%9},{%0,%1,%2,%3};"
        : "+f"(d[0]), "+f"(d[1]), "+f"(d[2]), "+f"(d[3])
        : "r"(a[0]), "r"(a[1]), "r"(a[2]), "r"(a[3]), "r"(b0), "r"(b1));
}
__device__ __forceinline__ uint32_t amat_addr(uint32_t base, int R0, int ci0, int lane) {
    int sel = lane >> 3;
    int r = R0 + (lane & 7) + ((sel & 1) << 3);
    int cb = (ci0 + ((sel >> 1) << 3)) * 2;
    return base + r * 256 + (cb ^ ((r & 7) << 4));
}
__device__ __forceinline__ void cp16s(uint32_t dst, const void* src) {
    asm volatile("cp.async.ca.shared.global [%0], [%1], 16;" :: "r"(dst), "l"(src));
}
#define CP_COMMIT() asm volatile("cp.async.commit_group;")
#define CP_WAIT2()  asm volatile("cp.async.wait_group 2;")
#define CP_WAIT1()  asm volatile("cp.async.wait_group 1;")
#define CP_WAIT0()  asm volatile("cp.async.wait_group 0;")

__global__ void __launch_bounds__(256, 1)
moe_main(const float* __restrict__ x,
         const float* __restrict__ bc_all, const float* __restrict__ bp_all,
         float* __restrict__ out) {
    extern __shared__ char smem[];
    const uint32_t sb = (uint32_t)__cvta_generic_to_shared(smem);
    float* swg   = (float*)(smem + SWG);
    float* spart = (float*)(smem + SPARTB);
    float* ssc   = (float*)(smem + SSCB);

    const int tid  = threadIdx.x;
    const int lane = tid & 31;
    const int warp = tid >> 5;
    const int wq = warp >> 1;          // px group of 32
    const int wh = warp & 1;           // co half
    const int blk  = blockIdx.x;
    const int b    = blk >> 5;
    const int row0 = (blk & 31) * 2;
    const int gq = lane >> 2, t4 = lane & 3;

    if (tid < 32) {
        int g = tid >> 3, e = tid & 7;
        swg[tid] = g_w[(g * 8 + b) * 8 + e];
    }

    // ---- x strip (4 halo rows, 66 cols, 128 ci), fp16 swizzled ----
    {
        const float* xb = x + (size_t)b * IMG;
        for (int it = 0; it < 64; ++it) {
            int rid = warp + it * 8;          // gry*128 + ci
            int gry = rid >> 7, ci = rid & 127;
            int gr = row0 - 1 + gry;
#pragma unroll
            for (int cl = 0; cl < 3; ++cl) {
                int c = lane + cl * 32;
                if (cl == 2 && lane >= 2) break;
                int gc = c - 1;
                float v = 0.f;
                if ((unsigned)gr < 64u && (unsigned)gc < 64u)
                    v = xb[ci * HWPIX + gr * 64 + gc];
                int R = gry * 66 + c;
                uint32_t off = R * 256 + ((ci * 2) ^ ((R & 7) << 4));
                *(__half*)(smem + SXH + off) = __float2half_rn(v);
            }
        }
    }

    float acc[2][8][4];

    for (int e = 0; e < EE; ++e) {
        float we0 = swg[e], we1 = swg[8 + e], we2 = swg[16 + e], we3 = swg[24 + e];
        __syncthreads();
        if (we0 == 0.f && we1 == 0.f && we2 == 0.f && we3 == 0.f) continue;

        auto loadW = [&](int cc, int bf) {
            const uint32_t* src = g_wc_f16 + (size_t)(e * 18 + cc) * 4096;
#pragma unroll
            for (int k = 0; k < 4; ++k) {
                int i = tid + k * 256;
                cp16s(sb + WOFF + bf * 16384 + i * 16, src + i * 4);
            }
            CP_COMMIT();
        };

        loadW(0, 0);
        loadW(1, 1);
        loadW(2, 2);
#pragma unroll
        for (int pm = 0; pm < 2; ++pm)
#pragma unroll
            for (int f = 0; f < 8; ++f)
#pragma unroll
                for (int i = 0; i < 4; ++i) acc[pm][f][i] = 0.f;

        // ---- GEMM1: 18 chunks, quad-buffered, prefetch distance 3 ----
        for (int cc = 0; cc < 18; ++cc) {
            if (cc < 16) { CP_WAIT2(); } else if (cc == 16) { CP_WAIT1(); } else { CP_WAIT0(); }
            __syncthreads();
            if (cc + 3 < 18) loadW(cc + 3, (cc + 3) & 3);

            const int j = cc >> 1;
            const int ky = j / 3, kx = j - 3 * (j / 3);
            const int h = cc & 1;
            const uint32_t whb = sb + WOFF + (cc & 3) * 16384;
#pragma unroll
            for (int ks = 0; ks < 4; ++ks) {
                const int ci0 = h * 64 + ks * 16;
                uint32_t ah[2][4];
#pragma unroll
                for (int pm = 0; pm < 2; ++pm) {
                    int P0 = wq * 32 + pm * 16;
                    int R0 = ((P0 >> 6) + ky) * 66 + (P0 & 63) + kx;
                    ldsm4(amat_addr(sb + SXH, R0, ci0, lane), ah[pm][0], ah[pm][1], ah[pm][2], ah[pm][3]);
                }
#pragma unroll
                for (int nn = 0; nn < 4; ++nn) {
                    const int co0 = wh * 64 + nn * 16;
                    uint32_t bh0, bh1, bh2, bh3;
                    ldsm4t(amat_addr(whb, ks * 16, co0, lane), bh0, bh1, bh2, bh3);
#pragma unroll
                    for (int pm = 0; pm < 2; ++pm) {
                        mma_fp(acc[pm][nn * 2], ah[pm], bh0, bh1);
                        mma_fp(acc[pm][nn * 2 + 1], ah[pm], bh2, bh3);
                    }
                }
            }
        }
        __syncthreads();   // all buffers free

        // prefetch both W_proj half-images into buffers 2,3
        {
            const uint32_t* pH = g_wp_f16 + (size_t)e * 8192;
#pragma unroll
            for (int k = 0; k < 8; ++k) {
                int i = tid + k * 256;            // 0..2047 -> 32KB
                cp16s(sb + WOFF + 32768 + i * 16, pH + i * 4);
            }
            CP_COMMIT();
        }

        // ---- bias + per-pixel sum of squares ----
#pragma unroll
        for (int pm = 0; pm < 2; ++pm) {
            float sa = 0.f, sb2 = 0.f;
#pragma unroll
            for (int f = 0; f < 8; ++f) {
                int co = wh * 64 + f * 8 + t4 * 2;
                float bc0 = __ldg(&bc_all[e * CC + co]);
                float bc1 = __ldg(&bc_all[e * CC + co + 1]);
                acc[pm][f][0] += bc0; acc[pm][f][1] += bc1;
                acc[pm][f][2] += bc0; acc[pm][f][3] += bc1;
                sa = fmaf(acc[pm][f][0], acc[pm][f][0], sa);
                sa = fmaf(acc[pm][f][1], acc[pm][f][1], sa);
                sb2 = fmaf(acc[pm][f][2], acc[pm][f][2], sb2);
                sb2 = fmaf(acc[pm][f][3], acc[pm][f][3], sb2);
            }
            sa += __shfl_xor_sync(0xffffffffu, sa, 1);
            sa += __shfl_xor_sync(0xffffffffu, sa, 2);
            sb2 += __shfl_xor_sync(0xffffffffu, sb2, 1);
            sb2 += __shfl_xor_sync(0xffffffffu, sb2, 2);
            if (t4 == 0) {
                int pxa = wq * 32 + pm * 16 + gq;
                spart[wh * 128 + pxa] = sa;
                spart[wh * 128 + pxa + 8] = sb2;
            }
        }
        __syncthreads();
        if (tid < 128) {
            float sn = spart[tid] + spart[128 + tid];
            ssc[tid] = sn / (1.f + sn) / (sqrtf(sn) + 1e-8f);
        }
        __syncthreads();

        // ---- scale + stage u into buffers 0,1 (128 px rows x 256B, swizzled) ----
#pragma unroll
        for (int pm = 0; pm < 2; ++pm) {
            int pxa = wq * 32 + pm * 16 + gq;
            float s0 = ssc[pxa], s1 = ssc[pxa + 8];
#pragma unroll
            for (int f = 0; f < 8; ++f) {
                int cb = (wh * 64 + f * 8 + t4 * 2) * 2;   // byte col (ci*2)
                uint32_t w0 = packh2(acc[pm][f][0] * s0, acc[pm][f][1] * s0);
                uint32_t o0 = pxa * 256 + (cb ^ ((pxa & 7) << 4));
                *(uint32_t*)(smem + WOFF + o0) = w0;
                uint32_t w1 = packh2(acc[pm][f][2] * s1, acc[pm][f][3] * s1);
                int px2 = pxa + 8;
                uint32_t o1 = px2 * 256 + (cb ^ ((px2 & 7) << 4));
                *(uint32_t*)(smem + WOFF + o1) = w1;
            }
        }
        CP_WAIT0();
        __syncthreads();

        // ---- GEMM2: K=128, single pass (u in bufs 0-1, Wp in bufs 2-3) ----
#pragma unroll
        for (int pm = 0; pm < 2; ++pm)
#pragma unroll
            for (int f = 0; f < 8; ++f)
#pragma unroll
                for (int i = 0; i < 4; ++i) acc[pm][f][i] = 0.f;
#pragma unroll
        for (int ks = 0; ks < 8; ++ks) {
            uint32_t ah[2][4];
#pragma unroll
            for (int pm = 0; pm < 2; ++pm) {
                int R0 = wq * 32 + pm * 16;
                ldsm4(amat_addr(sb + WOFF, R0, ks * 16, lane), ah[pm][0], ah[pm][1], ah[pm][2], ah[pm][3]);
            }
            uint32_t wpb = sb + WOFF + 32768 + (ks >> 2) * 16384;
            int kr = (ks & 3) * 16;
#pragma unroll
            for (int nn = 0; nn < 4; ++nn) {
                int co0 = wh * 64 + nn * 16;
                uint32_t bh0, bh1, bh2, bh3;
                ldsm4t(amat_addr(wpb, kr, co0, lane), bh0, bh1, bh2, bh3);
#pragma unroll
                for (int pm = 0; pm < 2; ++pm) {
                    mma_fp(acc[pm][nn * 2], ah[pm], bh0, bh1);
                    mma_fp(acc[pm][nn * 2 + 1], ah[pm], bh2, bh3);
                }
            }
        }
        __syncthreads();   // done reading u/Wp; region reusable for staging

        // ---- v = acc + bp -> scratch (staged, coalesced float4 writes) ----
        float* stg = (float*)(smem + WOFF);   // [64 co][132]
        for (int r = 0; r < 2; ++r) {
            if (wh == r) {
#pragma unroll
                for (int pm = 0; pm < 2; ++pm) {
                    int pxa = wq * 32 + pm * 16 + gq;
#pragma unroll
                    for (int f = 0; f < 8; ++f) {
                        int cl = f * 8 + t4 * 2;
                        float bp0 = __ldg(&bp_all[e * CC + r * 64 + cl]);
                        float bp1 = __ldg(&bp_all[e * CC + r * 64 + cl + 1]);
                        stg[cl * 132 + pxa]           = acc[pm][f][0] + bp0;
                        stg[(cl + 1) * 132 + pxa]     = acc[pm][f][1] + bp1;
                        stg[cl * 132 + pxa + 8]       = acc[pm][f][2] + bp0;
                        stg[(cl + 1) * 132 + pxa + 8] = acc[pm][f][3] + bp1;
                    }
                }
            }
            __syncthreads();
            float* dst = g_scr + (size_t)(e * NBLK + blk) * 16384 + r * 64 * 128;
#pragma unroll
            for (int k = 0; k < 8; ++k) {
                int i = tid + k * 256;
                int cl = i >> 5, p4 = (i & 31) * 4;
                float4 v = *(float4*)&stg[cl * 132 + p4];
                *(float4*)&dst[cl * 128 + p4] = v;
            }
            __syncthreads();
        }
    }

    // ---- combine: y_g = sum_e w_ge * v_e ----
    __syncthreads();
#pragma unroll 1
    for (int k = 0; k < 16; ++k) {
        int i = tid + k * 256;
        int co = i >> 5, p4 = (i & 31) * 4;
        float4 y0 = {0, 0, 0, 0}, y1 = y0, y2 = y0, y3 = y0;
#pragma unroll
        for (int e = 0; e < EE; ++e) {
            float a0 = swg[e], a1 = swg[8 + e], a2 = swg[16 + e], a3 = swg[24 + e];
            if (a0 == 0.f && a1 == 0.f && a2 == 0.f && a3 == 0.f) continue;
            float4 v = *(const float4*)(g_scr + (size_t)(e * NBLK + blk) * 16384 + co * 128 + p4);
            y0.x += a0 * v.x; y0.y += a0 * v.y; y0.z += a0 * v.z; y0.w += a0 * v.w;
            y1.x += a1 * v.x; y1.y += a1 * v.y; y1.z += a1 * v.z; y1.w += a1 * v.w;
            y2.x += a2 * v.x; y2.y += a2 * v.y; y2.z += a2 * v.z; y2.w += a2 * v.w;
            y3.x += a3 * v.x; y3.y += a3 * v.y; y3.z += a3 * v.z; y3.w += a3 * v.w;
        }
        int r2 = p4 >> 6, col = p4 & 63;
        size_t gidx = (size_t)b * IMG + (size_t)co * HWPIX + (size_t)(row0 + r2) * 64 + col;
        *(float4*)(out + gidx) = y0;
        *(float4*)(out + YSZ + gidx) = y1;
        *(float4*)(out + 2 * YSZ + gidx) = y2;
        *(float4*)(out + 3 * YSZ + gidx) = y3;
    }
}

// ---------------------------------------------------------------------------
extern "C" void kernel_launch(void* const* d_in, const int* in_sizes, int n_in,
                              void* d_out, int out_size) {
    const float* x  = (const float*)d_in[0];
    const float* g1 = (const float*)d_in[1];
    const float* g2 = (const float*)d_in[2];
    const float* g3 = (const float*)d_in[3];
    const float* g4 = (const float*)d_in[4];
    const float* Wc = (const float*)d_in[5];
    const float* bc = (const float*)d_in[6];
    const float* Wp = (const float*)d_in[7];
    const float* bp = (const float*)d_in[8];
    float* out = (float*)d_out;

    cudaFuncSetAttribute(moe_main, cudaFuncAttributeMaxDynamicSharedMemorySize, SMEM_BYTES);

    mean_kernel<<<BB * CC, 256>>>(x);
    gate_kernel<<<1, 32>>>(g1, g2, g3, g4, out + (out_size - 1));
    prep_wc<<<EE * 18, 256>>>(Wc);
    prep_wp<<<EE * 2, 256>>>(Wp);
    moe_main<<<NBLK, 256, SMEM_BYTES>>>(x, bc, bp, out);
}